// round 12
// baseline (speedup 1.0000x reference)
#include <cuda_runtime.h>
#include <cuda_bf16.h>
#include <math.h>
#include <stdint.h>

// Problem constants
#define Bb 2
#define Tt 8
#define Mm 512
#define Dd 1024
#define Hh 1024
#define WIN 3
#define KNN 8
#define NROWS (Bb*Tt*Mm)      /* 8192 */
#define WM (WIN*Mm)           /* 1536 */
#define LN_EPS 1e-5f
#define KT 3072               /* tripled K: [hi|lo|hi] x [hi|hi|lo] */

// ---------------- scratch (device globals; no allocation allowed) -------------
__device__ float g_sim[(size_t)NROWS*WM];
__device__ float g_vals[NROWS*KNN];
__device__ int   g_idx[NROWS*KNN];
__device__ float g_X[NROWS*Dd];
__device__ float g_gi[(size_t)NROWS*3*Hh];
__device__ float g_gh[(size_t)Bb*Mm*3*Hh];
__device__ float g_mem[Bb*Mm*Hh];
__device__ float g_wksum[Dd];
__device__ float g_s0[Bb*Tt];

// bf16 tripled-K operand copies (16B aligned for uint4 loads)
__device__ __align__(16) __nv_bfloat16 g_znA[(size_t)NROWS*KT];
__device__ __align__(16) __nv_bfloat16 g_znB[(size_t)NROWS*KT];
__device__ __align__(16) __nv_bfloat16 g_zA [(size_t)NROWS*KT];
__device__ __align__(16) __nv_bfloat16 g_aggA[(size_t)NROWS*KT];
__device__ __align__(16) __nv_bfloat16 g_XlnA[(size_t)NROWS*KT];
__device__ __align__(16) __nv_bfloat16 g_inpA[(size_t)NROWS*KT];
__device__ __align__(16) __nv_bfloat16 g_memAt[(size_t)Tt*Bb*Mm*KT]; /* per-t mem */
__device__ __align__(16) __nv_bfloat16 g_WqB [(size_t)Dd*KT];
__device__ __align__(16) __nv_bfloat16 g_WvB [(size_t)Dd*KT];
__device__ __align__(16) __nv_bfloat16 g_WoutB[(size_t)Dd*KT];
__device__ __align__(16) __nv_bfloat16 g_WihB[(size_t)3*Hh*KT];
__device__ __align__(16) __nv_bfloat16 g_WhhB[(size_t)3*Hh*KT];
__device__ __align__(16) __nv_bfloat16 g_WmfB[(size_t)Dd*KT];

// valid (t, w) pairs
__constant__ int c_pt[21] = {0,1,1,2,2,2,3,3,3,4,4,4,5,5,5,6,6,6,7,7,7};
__constant__ int c_pw[21] = {0,0,1,0,1,2,0,1,2,0,1,2,0,1,2,0,1,2,0,1,2};

// ============================ helpers =========================================
__device__ __forceinline__ uint32_t smem_u32(const void* p){
    uint32_t a;
    asm("{ .reg .u64 t; cvta.to.shared.u64 t, %1; cvt.u32.u64 %0, t; }"
        : "=r"(a) : "l"(p));
    return a;
}
__device__ __forceinline__ void split2(float x, __nv_bfloat16& h, __nv_bfloat16& l){
    h = __float2bfloat16(x);
    l = __float2bfloat16(x - __bfloat162float(h));
}
#define LDSM4(r, a)                                                             \
    asm volatile("ldmatrix.sync.aligned.m8n8.x4.shared.b16 {%0,%1,%2,%3}, [%4];"\
        : "=r"((r)[0]), "=r"((r)[1]), "=r"((r)[2]), "=r"((r)[3]) : "r"(a))
#define MMA16816(c, a, b0v, b1v)                                                \
    asm volatile("mma.sync.aligned.m16n8k16.row.col.f32.bf16.bf16.f32 "         \
        "{%0,%1,%2,%3}, {%4,%5,%6,%7}, {%8,%9}, {%0,%1,%2,%3};"                 \
        : "+f"((c)[0]), "+f"((c)[1]), "+f"((c)[2]), "+f"((c)[3])                \
        : "r"((a)[0]), "r"((a)[1]), "r"((a)[2]), "r"((a)[3]),                   \
          "r"(b0v), "r"(b1v))

// ============================ mma.sync GEMM ===================================
// C[i,j] = sum A[i,:]*W[j,:], bf16 tripled-K (KT=3072 per segment).
// BM=128, BN=128, BK=32. 8 warps (2m x 4n), warp tile 64x32.
// smem: padded stride 80B per 32-elem bf16 row (conflict-free ldmatrix).
#define BM 128
#define BN 128
#define BK 32
#define SSTR 80
#define STG  (128*SSTR)        /* 10240 B per operand stage */

// tasks: 0=sim  1=X(z@Wq + agg@Wv)  2=inp(Xln@Wout, split-out)  3=gi(+b1)
//        4=gh(mem_t@Whh + b1)  5=out(memAt@Wmf + z + b1, batched over t)
__global__ __launch_bounds__(256,2) void gemm_mma(
    int task, int t, const float* __restrict__ b1,
    const float* __restrict__ zin, float* __restrict__ outp)
{
    __shared__ __align__(16) char smem[4*STG];
    const int tid  = threadIdx.x;
    const int wid  = tid >> 5, lane = tid & 31;
    const int brow = blockIdx.y * BM;
    const int bcol = blockIdx.x * BN;
    const int warp_m = (wid & 1) * 64;
    const int warp_n = (wid >> 1) * 32;

    const __nv_bfloat16 *A0=0, *A1=0, *W0=0, *W1=0;
    int nseg = 1, b = 0, w = 0, tt = 0;
    if (task == 0) {
        int bz = blockIdx.z; b = bz/21; int p = bz%21; tt = c_pt[p]; w = c_pw[p];
        A0 = g_znA + (size_t)((b*Tt+tt)*Mm + brow)*KT;
        W0 = g_znB + (size_t)((b*Tt+(tt-w))*Mm + bcol)*KT;
    } else if (task == 1) {
        A0 = g_zA   + (size_t)brow*KT; W0 = g_WqB + (size_t)bcol*KT;
        A1 = g_aggA + (size_t)brow*KT; W1 = g_WvB + (size_t)bcol*KT; nseg = 2;
    } else if (task == 2) {
        A0 = g_XlnA + (size_t)brow*KT; W0 = g_WoutB + (size_t)bcol*KT;
    } else if (task == 3) {
        A0 = g_inpA + (size_t)brow*KT; W0 = g_WihB + (size_t)bcol*KT;
    } else if (task == 4) {
        A0 = g_memAt + ((size_t)t*Bb*Mm + brow)*KT;
        W0 = g_WhhB + (size_t)bcol*KT;
    } else {
        A0 = g_memAt + (size_t)brow*KT;      // rows span all t (t-major)
        W0 = g_WmfB + (size_t)bcol*KT;
    }

    const uint32_t sbase = smem_u32(smem);
    const uint32_t sA[2] = {sbase,         sbase + 2*STG};
    const uint32_t sB[2] = {sbase + STG,   sbase + 3*STG};

    const int lr  = tid >> 2;            // 0..63
    const int lc  = (tid & 3) * 8;       // element col within BK
    const uint32_t sts_off = (uint32_t)lr*SSTR + (uint32_t)(tid & 3)*16;

    const uint32_t aRow  = (uint32_t)(warp_m + (lane & 15));
    const uint32_t bRow  = (uint32_t)(warp_n + (lane & 15));
    const uint32_t chnk  = (uint32_t)((lane >> 4) * 16);

    float acc[4][4][4];
    #pragma unroll
    for (int i=0;i<4;i++)
      #pragma unroll
      for (int j=0;j<4;j++)
        #pragma unroll
        for (int k=0;k<4;k++) acc[i][j][k] = 0.f;

    const int S = nseg * (KT/BK);
    uint4 ra0, ra1, rb0, rb1;

    // prologue: stage 0
    {
        ra0 = *(const uint4*)(A0 + (size_t)lr*KT + lc);
        ra1 = *(const uint4*)(A0 + (size_t)(lr+64)*KT + lc);
        rb0 = *(const uint4*)(W0 + (size_t)lr*KT + lc);
        rb1 = *(const uint4*)(W0 + (size_t)(lr+64)*KT + lc);
        *(uint4*)(smem + (sts_off))              = ra0;
        *(uint4*)(smem + (sts_off + 64*SSTR))    = ra1;
        *(uint4*)(smem + (STG + sts_off))        = rb0;
        *(uint4*)(smem + (STG + sts_off + 64*SSTR)) = rb1;
    }
    __syncthreads();

    for (int s = 0; s < S; s++) {
        const int buf = s & 1;
        if (s + 1 < S) {
            const int sn  = s + 1;
            const int seg = sn >= (KT/BK);
            const int k0  = (sn - seg*(KT/BK)) * BK;
            const __nv_bfloat16* Ab = (seg ? A1 : A0);
            const __nv_bfloat16* Wb = (seg ? W1 : W0);
            ra0 = *(const uint4*)(Ab + (size_t)lr*KT + k0 + lc);
            ra1 = *(const uint4*)(Ab + (size_t)(lr+64)*KT + k0 + lc);
            rb0 = *(const uint4*)(Wb + (size_t)lr*KT + k0 + lc);
            rb1 = *(const uint4*)(Wb + (size_t)(lr+64)*KT + k0 + lc);
        }
        #pragma unroll
        for (int kk = 0; kk < 2; kk++) {
            uint32_t afr[4][4], bfr[2][4];
            #pragma unroll
            for (int mt = 0; mt < 4; mt++)
                LDSM4(afr[mt], sA[buf] + (aRow + mt*16)*SSTR + kk*32 + chnk);
            #pragma unroll
            for (int nt = 0; nt < 2; nt++)
                LDSM4(bfr[nt], sB[buf] + (bRow + nt*16)*SSTR + kk*32 + chnk);
            #pragma unroll
            for (int mt = 0; mt < 4; mt++)
                #pragma unroll
                for (int n8 = 0; n8 < 4; n8++)
                    MMA16816(acc[mt][n8], afr[mt],
                             bfr[n8>>1][n8&1], bfr[n8>>1][2+(n8&1)]);
        }
        if (s + 1 < S) {
            const int nb = buf ^ 1;
            char* base = smem + (nb ? 2*STG : 0);
            *(uint4*)(base + sts_off)                 = ra0;
            *(uint4*)(base + sts_off + 64*SSTR)       = ra1;
            *(uint4*)(base + STG + sts_off)           = rb0;
            *(uint4*)(base + STG + sts_off + 64*SSTR) = rb1;
        }
        __syncthreads();
    }

    // ------------------------------ epilogue ----------------------------------
    const int l4 = lane >> 2;
    const int l2 = (lane & 3) * 2;
    #pragma unroll
    for (int mt = 0; mt < 4; mt++) {
        #pragma unroll
        for (int half = 0; half < 2; half++) {
            const int row = brow + warp_m + mt*16 + l4 + half*8;
            #pragma unroll
            for (int n8 = 0; n8 < 4; n8++) {
                const int col = bcol + warp_n + n8*8 + l2;
                float c0 = acc[mt][n8][half*2 + 0];
                float c1 = acc[mt][n8][half*2 + 1];
                if (task == 0) {
                    float* C = g_sim + (size_t)((b*Tt+tt)*Mm + row)*WM + w*Mm + col;
                    *(float2*)C = make_float2(c0, c1);
                } else if (task == 1) {
                    float* C = g_X + (size_t)row*Dd + col;
                    *(float2*)C = make_float2(c0, c1);
                } else if (task == 2) {
                    __nv_bfloat16* dst = g_inpA + (size_t)row*KT + col;
                    __nv_bfloat16 h0,l0,h1,l1;
                    split2(c0, h0, l0); split2(c1, h1, l1);
                    __nv_bfloat162 hh; hh.x = h0; hh.y = h1;
                    __nv_bfloat162 ll; ll.x = l0; ll.y = l1;
                    *(__nv_bfloat162*)(dst)        = hh;
                    *(__nv_bfloat162*)(dst + 1024) = ll;
                    *(__nv_bfloat162*)(dst + 2048) = hh;
                } else if (task == 3) {
                    float2 bb = *(const float2*)(b1 + col);
                    float* C = g_gi + (size_t)row*(3*Hh) + col;
                    *(float2*)C = make_float2(c0 + bb.x, c1 + bb.y);
                } else if (task == 4) {
                    float2 bb = *(const float2*)(b1 + col);
                    float* C = g_gh + (size_t)row*(3*Hh) + col;
                    *(float2*)C = make_float2(c0 + bb.x, c1 + bb.y);
                } else {
                    const int tg = row >> 10;          // row = t*1024 + i
                    const int i  = row & 1023;
                    const int bi = i >> 9, m = i & 511;
                    const size_t zr = (size_t)((bi*Tt + tg)*Mm + m)*Dd + col;
                    float2 zz = *(const float2*)(zin + zr);
                    float2 bb = *(const float2*)(b1 + col);
                    *(float2*)(outp + zr) = make_float2(c0 + zz.x + bb.x,
                                                        c1 + zz.y + bb.y);
                }
            }
        }
    }
}

// ============================ conversion kernels ==============================
__global__ void k_convB(const float* __restrict__ src, __nv_bfloat16* __restrict__ dst)
{
    int e = blockIdx.x*256 + threadIdx.x;
    int r = e >> 10, c = e & 1023;
    __nv_bfloat16 h, l; split2(src[e], h, l);
    size_t base = (size_t)r*KT;
    dst[base + c] = h; dst[base + 1024 + c] = h; dst[base + 2048 + c] = l;
}

// ============================ elementwise kernels =============================
// normalize -> znA/znB splits; also write raw-z A-split (fused old k_convA)
__global__ void k_normalize(const float* __restrict__ z)
{
    const int row = blockIdx.x, tid = threadIdx.x;
    __shared__ float red[256];
    const float* src = z + (size_t)row*Dd;
    float s = 0.f;
    for (int d = tid; d < Dd; d += 256) { float v = src[d]; s += v*v; }
    red[tid] = s; __syncthreads();
    for (int st = 128; st > 0; st >>= 1) { if (tid < st) red[tid] += red[tid+st]; __syncthreads(); }
    const float inv = 1.0f / fmaxf(sqrtf(red[0]), 1e-12f);
    const size_t base = (size_t)row*KT;
    for (int d = tid; d < Dd; d += 256) {
        float zr = src[d];
        float v = zr*inv;
        __nv_bfloat16 h, l; split2(v, h, l);
        g_znA[base + d] = h; g_znA[base + 1024 + d] = l; g_znA[base + 2048 + d] = h;
        g_znB[base + d] = h; g_znB[base + 1024 + d] = h; g_znB[base + 2048 + d] = l;
        __nv_bfloat16 zh, zl; split2(zr, zh, zl);
        g_zA[base + d] = zh; g_zA[base + 1024 + d] = zl; g_zA[base + 2048 + d] = zh;
    }
}

__global__ void k_wksum(const float* __restrict__ Wk)
{
    int d = blockIdx.x*blockDim.x + threadIdx.x;
    if (d < Dd) {
        float s = 0.f;
        for (int r = 0; r < Dd; r++) s += Wk[(size_t)r*Dd + d];
        g_wksum[d] = s;
    }
}

__global__ void k_s0(const float* __restrict__ z, const float* __restrict__ Watt_q)
{
    const int bt = blockIdx.x, tid = threadIdx.x;
    __shared__ float red[256];
    const float* src = z + (size_t)(bt*Mm)*Dd;
    float s = 0.f;
    for (int d = tid; d < Dd; d += 256) s += src[d]*Watt_q[d];
    red[tid] = s; __syncthreads();
    for (int st = 128; st > 0; st >>= 1) { if (tid < st) red[tid] += red[tid+st]; __syncthreads(); }
    if (tid == 0) g_s0[bt] = red[0];
}

// warp-shuffle argmax top-k (preserves smallest-index tie-break)
__global__ void k_topk(void)
{
    const int row = blockIdx.x, tid = threadIdx.x;
    const int t = (row / Mm) % Tt;
    const int limit = (t >= 2 ? 3 : t + 1) * Mm;
    const int lane = tid & 31, wid = tid >> 5;
    __shared__ float sv[WM];
    __shared__ float wv[8];
    __shared__ int   wx[8];
    for (int i = tid; i < limit; i += 256) sv[i] = g_sim[(size_t)row*WM + i];
    __syncthreads();
    for (int k = 0; k < KNN; k++) {
        float bv = -INFINITY; int bi = 0x7FFFFFFF;
        for (int i = tid; i < limit; i += 256) {
            float v = sv[i];
            if (v > bv) { bv = v; bi = i; }     // strided ascending: first max = min idx
        }
        #pragma unroll
        for (int o = 16; o > 0; o >>= 1) {
            float v2 = __shfl_down_sync(0xffffffff, bv, o);
            int   i2 = __shfl_down_sync(0xffffffff, bi, o);
            if (v2 > bv || (v2 == bv && i2 < bi)) { bv = v2; bi = i2; }
        }
        if (lane == 0) { wv[wid] = bv; wx[wid] = bi; }
        __syncthreads();
        if (tid == 0) {
            float fv = wv[0]; int fi = wx[0];
            #pragma unroll
            for (int j = 1; j < 8; j++)
                if (wv[j] > fv || (wv[j] == fv && wx[j] < fi)) { fv = wv[j]; fi = wx[j]; }
            g_vals[row*KNN+k] = fv;
            g_idx [row*KNN+k] = fi;
            sv[fi] = -INFINITY;
        }
        __syncthreads();
    }
}

__global__ void k_attn_agg(const float* __restrict__ z)
{
    const int row = blockIdx.x, tid = threadIdx.x;   // 128 threads
    const int bt = row / Mm;
    const int t = bt % Tt, b = bt / Tt;
    __shared__ float kf[KNN][Dd];
    __shared__ float red[128];
    __shared__ float kh[KNN], alpha[KNN];
    for (int k = 0; k < KNN; k++) {
        int id = g_idx[row*KNN+k];
        int w = id / Mm, j = id - w*Mm;
        int tt = t - w; if (tt < 0) tt = 0;
        const float* src = z + (size_t)((b*Tt+tt)*Mm + j)*Dd;
        float part = 0.f;
        for (int d = tid; d < Dd; d += 128) { float v = src[d]; kf[k][d] = v; part += v*g_wksum[d]; }
        red[tid] = part; __syncthreads();
        for (int s = 64; s > 0; s >>= 1) { if (tid < s) red[tid] += red[tid+s]; __syncthreads(); }
        if (tid == 0) kh[k] = red[0];
        __syncthreads();
    }
    if (tid == 0) {
        float s = g_s0[bt];
        float l[KNN], mx = -INFINITY;
        for (int k = 0; k < KNN; k++) { l[k] = s*kh[k]; mx = fmaxf(mx, l[k]); }
        float sum = 0.f;
        for (int k = 0; k < KNN; k++) { l[k] = expf(l[k]-mx); sum += l[k]; }
        for (int k = 0; k < KNN; k++)
            alpha[k] = 0.5f*g_vals[row*KNN+k] + 0.5f*(l[k]/sum);
    }
    __syncthreads();
    const size_t base = (size_t)row*KT;
    for (int d = tid; d < Dd; d += 128) {
        float a = 0.f;
        #pragma unroll
        for (int k = 0; k < KNN; k++) a += alpha[k]*kf[k][d];
        __nv_bfloat16 h, l; split2(a, h, l);
        g_aggA[base + d] = h; g_aggA[base + 1024 + d] = l; g_aggA[base + 2048 + d] = h;
    }
}

__global__ void k_layernorm(const float* __restrict__ lnw, const float* __restrict__ lnb)
{
    const int row = blockIdx.x, tid = threadIdx.x;
    __shared__ float xr[Dd];
    __shared__ float red[256];
    const float* p = g_X + (size_t)row*Dd;
    float s = 0.f;
    for (int d = tid; d < Dd; d += 256) { float v = p[d]; xr[d] = v; s += v; }
    red[tid] = s; __syncthreads();
    for (int st = 128; st > 0; st >>= 1) { if (tid < st) red[tid] += red[tid+st]; __syncthreads(); }
    const float mu = red[0] * (1.0f/Dd);
    __syncthreads();
    float v2 = 0.f;
    for (int d = tid; d < Dd; d += 256) { float dv = xr[d]-mu; v2 += dv*dv; }
    red[tid] = v2; __syncthreads();
    for (int st = 128; st > 0; st >>= 1) { if (tid < st) red[tid] += red[tid+st]; __syncthreads(); }
    const float inv = 1.0f / sqrtf(red[0]*(1.0f/Dd) + LN_EPS);
    const size_t base = (size_t)row*KT;
    for (int d = tid; d < Dd; d += 256) {
        float v = (xr[d]-mu)*inv*lnw[d] + lnb[d];
        __nv_bfloat16 h, l; split2(v, h, l);
        g_XlnA[base + d] = h; g_XlnA[base + 1024 + d] = l; g_XlnA[base + 2048 + d] = h;
    }
}

__global__ void k_zero_mem(void)
{
    int e = blockIdx.x*256 + threadIdx.x;
    if (e < Bb*Mm*Hh) g_mem[e] = 0.f;
}

__global__ void k_init_gh(const float* __restrict__ bhh)
{
    int e = blockIdx.x*256 + threadIdx.x;
    g_gh[e] = bhh[e % (3*Hh)];
}

__global__ void k_gru(int t)
{
    const int e = blockIdx.x*256 + threadIdx.x;       // 0 .. B*M*H-1
    const int i = e >> 10;
    const int hc = e & (Hh-1);
    const int b = i >> 9;
    const size_t gir = (size_t)(i + b*(Tt-1)*Mm + t*Mm);
    const float* gi = g_gi + gir*(3*Hh);
    const float* gh = g_gh + (size_t)i*(3*Hh);
    float r  = 1.f/(1.f + expf(-(gi[hc]        + gh[hc])));
    float zg = 1.f/(1.f + expf(-(gi[Hh+hc]     + gh[Hh+hc])));
    float n  = tanhf(gi[2*Hh+hc] + r*gh[2*Hh+hc]);
    size_t mo = (size_t)i*Hh + hc;
    float old = g_mem[mo];
    float nm = (1.f - zg)*n + zg*old;
    g_mem[mo] = nm;
    __nv_bfloat16 h, l; split2(nm, h, l);
    const size_t base = ((size_t)t*Bb*Mm + i)*KT;
    g_memAt[base + hc] = h; g_memAt[base + 1024 + hc] = l; g_memAt[base + 2048 + hc] = h;
}

__global__ void k_copy_mem(float* __restrict__ out_mem)
{
    int e = blockIdx.x*256 + threadIdx.x;
    if (e < Bb*Mm*Hh) out_mem[e] = g_mem[e];
}

// ================================ launch ======================================
extern "C" void kernel_launch(void* const* d_in, const int* in_sizes, int n_in,
                              void* d_out, int out_size)
{
    const float* z      = (const float*)d_in[0];
    const float* Wq     = (const float*)d_in[1];
    const float* Wv     = (const float*)d_in[2];
    const float* Wout   = (const float*)d_in[3];
    const float* ln_w   = (const float*)d_in[4];
    const float* ln_b   = (const float*)d_in[5];
    const float* Watt_q = (const float*)d_in[6];
    const float* Watt_k = (const float*)d_in[7];
    const float* W_ih   = (const float*)d_in[8];
    const float* W_hh   = (const float*)d_in[9];
    const float* b_ih   = (const float*)d_in[10];
    const float* b_hh   = (const float*)d_in[11];
    const float* W_mf   = (const float*)d_in[12];
    const float* b_mf   = (const float*)d_in[13];
    float* out     = (float*)d_out;
    float* out_h   = out;                            // (B,T,M,D)
    float* out_mem = out + (size_t)NROWS*Dd;         // (B,M,H)

    __nv_bfloat16 *pWqB, *pWvB, *pWoutB, *pWihB, *pWhhB, *pWmfB;
    cudaGetSymbolAddress((void**)&pWqB,   g_WqB);
    cudaGetSymbolAddress((void**)&pWvB,   g_WvB);
    cudaGetSymbolAddress((void**)&pWoutB, g_WoutB);
    cudaGetSymbolAddress((void**)&pWihB,  g_WihB);
    cudaGetSymbolAddress((void**)&pWhhB,  g_WhhB);
    cudaGetSymbolAddress((void**)&pWmfB,  g_WmfB);

    // ---- conversions + parallel precompute ----
    k_normalize<<<NROWS, 256>>>(z);                  // also writes g_zA split
    k_convB<<<Dd*Dd/256, 256>>>(Wq,   pWqB);
    k_convB<<<Dd*Dd/256, 256>>>(Wv,   pWvB);
    k_convB<<<Dd*Dd/256, 256>>>(Wout, pWoutB);
    k_convB<<<3*Hh*Dd/256, 256>>>(W_ih, pWihB);
    k_convB<<<3*Hh*Dd/256, 256>>>(W_hh, pWhhB);
    k_convB<<<Dd*Dd/256, 256>>>(W_mf, pWmfB);
    k_wksum<<<Dd/256, 256>>>(Watt_k);
    k_s0<<<Bb*Tt, 256>>>(z, Watt_q);

    // sims (42 Gram blocks)
    gemm_mma<<<dim3(Mm/BN, Mm/BM, Bb*21), 256>>>(0, 0, nullptr, nullptr, nullptr);
    k_topk<<<NROWS, 256>>>();
    k_attn_agg<<<NROWS, 128>>>(z);

    // X = z@Wq^T + agg@Wv^T  -> g_X
    gemm_mma<<<dim3(Dd/BN, NROWS/BM), 256>>>(1, 0, nullptr, nullptr, nullptr);
    k_layernorm<<<NROWS, 256>>>(ln_w, ln_b);
    // inp = Xln@Wout^T (split out) ; gi = inp@W_ih^T + b_ih
    gemm_mma<<<dim3(Dd/BN, NROWS/BM), 256>>>(2, 0, nullptr, nullptr, nullptr);
    gemm_mma<<<dim3(3*Hh/BN, NROWS/BM), 256>>>(3, 0, b_ih, nullptr, nullptr);

    // ---- sequential GRU (gh-only GEMM; Wmf batched afterwards) ----
    k_zero_mem<<<(Bb*Mm*Hh)/256, 256>>>();
    k_init_gh<<<(Bb*Mm*3*Hh)/256, 256>>>(b_hh);
    for (int t = 0; t < Tt; t++) {
        k_gru<<<(Bb*Mm*Hh)/256, 256>>>(t);           // mem <- mem_{t+1}, store memAt[t]
        if (t < Tt-1)                                 // gh for next step only
            gemm_mma<<<dim3(3*Hh/BN, (Bb*Mm)/BM), 256>>>(4, t, b_hh, nullptr, nullptr);
    }
    // out_h[b,t,m,:] = z + mem_t@Wmf^T + b_mf  (one batched GEMM over all t)
    gemm_mma<<<dim3(Dd/BN, (Tt*Bb*Mm)/BM), 256>>>(5, 0, b_mf, z, out_h);
    k_copy_mem<<<(Bb*Mm*Hh)/256, 256>>>(out_mem);
}

// round 14
// speedup vs baseline: 1.0287x; 1.0287x over previous
#include <cuda_runtime.h>
#include <cuda_bf16.h>
#include <math.h>
#include <stdint.h>

// Problem constants
#define Bb 2
#define Tt 8
#define Mm 512
#define Dd 1024
#define Hh 1024
#define WIN 3
#define KNN 8
#define NROWS (Bb*Tt*Mm)      /* 8192 */
#define WM (WIN*Mm)           /* 1536 */
#define LN_EPS 1e-5f
#define KT 3072               /* tripled K: [hi|lo|hi] x [hi|hi|lo] */
#define KT2 2048              /* 2-term prefix: [hi|lo] x [hi|hi] (drops A*Blo ~2e-3) */

// ---------------- scratch (device globals; no allocation allowed) -------------
__device__ float g_sim[(size_t)NROWS*WM];
__device__ float g_vals[NROWS*KNN];
__device__ int   g_idx[NROWS*KNN];
__device__ float g_X[NROWS*Dd];
__device__ float g_gi[(size_t)NROWS*3*Hh];
__device__ float g_gh[(size_t)Bb*Mm*3*Hh];
__device__ float g_mem[Bb*Mm*Hh];
__device__ float g_wksum[Dd];
__device__ float g_s0[Bb*Tt];

// bf16 tripled-K operand copies (16B aligned for cp.async 16B chunks)
__device__ __align__(16) __nv_bfloat16 g_znA[(size_t)NROWS*KT];
__device__ __align__(16) __nv_bfloat16 g_znB[(size_t)NROWS*KT];
__device__ __align__(16) __nv_bfloat16 g_zA [(size_t)NROWS*KT];
__device__ __align__(16) __nv_bfloat16 g_aggA[(size_t)NROWS*KT];
__device__ __align__(16) __nv_bfloat16 g_XlnA[(size_t)NROWS*KT];
__device__ __align__(16) __nv_bfloat16 g_inpA[(size_t)NROWS*KT];
__device__ __align__(16) __nv_bfloat16 g_memAt[(size_t)Tt*Bb*Mm*KT]; /* per-t mem */
__device__ __align__(16) __nv_bfloat16 g_WqB [(size_t)Dd*KT];
__device__ __align__(16) __nv_bfloat16 g_WvB [(size_t)Dd*KT];
__device__ __align__(16) __nv_bfloat16 g_WoutB[(size_t)Dd*KT];
__device__ __align__(16) __nv_bfloat16 g_WihB[(size_t)3*Hh*KT];
__device__ __align__(16) __nv_bfloat16 g_WhhB[(size_t)3*Hh*KT];
__device__ __align__(16) __nv_bfloat16 g_WmfB[(size_t)Dd*KT];

// valid (t, w) pairs
__constant__ int c_pt[21] = {0,1,1,2,2,2,3,3,3,4,4,4,5,5,5,6,6,6,7,7,7};
__constant__ int c_pw[21] = {0,0,1,0,1,2,0,1,2,0,1,2,0,1,2,0,1,2,0,1,2};

// ============================ helpers =========================================
__device__ __forceinline__ uint32_t smem_u32(const void* p){
    uint32_t a;
    asm("{ .reg .u64 t; cvta.to.shared.u64 t, %1; cvt.u32.u64 %0, t; }"
        : "=r"(a) : "l"(p));
    return a;
}
__device__ __forceinline__ void split2(float x, __nv_bfloat16& h, __nv_bfloat16& l){
    h = __float2bfloat16(x);
    l = __float2bfloat16(x - __bfloat162float(h));
}
__device__ __forceinline__ void cp16(uint32_t dst, const void* src){
    asm volatile("cp.async.cg.shared.global [%0], [%1], 16;"
                 :: "r"(dst), "l"(src));
}
#define CP_COMMIT() asm volatile("cp.async.commit_group;" ::: "memory")
#define CP_WAIT(n)  asm volatile("cp.async.wait_group %0;" :: "n"(n) : "memory")
#define LDSM4(r, a)                                                             \
    asm volatile("ldmatrix.sync.aligned.m8n8.x4.shared.b16 {%0,%1,%2,%3}, [%4];"\
        : "=r"((r)[0]), "=r"((r)[1]), "=r"((r)[2]), "=r"((r)[3]) : "r"(a))
#define MMA16816(c, a, b0v, b1v)                                                \
    asm volatile("mma.sync.aligned.m16n8k16.row.col.f32.bf16.bf16.f32 "         \
        "{%0,%1,%2,%3}, {%4,%5,%6,%7}, {%8,%9}, {%0,%1,%2,%3};"                 \
        : "+f"((c)[0]), "+f"((c)[1]), "+f"((c)[2]), "+f"((c)[3])                \
        : "r"((a)[0]), "r"((a)[1]), "r"((a)[2]), "r"((a)[3]),                   \
          "r"(b0v), "r"(b1v))

// ============================ mma.sync GEMM ===================================
// C[i,j] = sum A[i,:]*W[j,:], bf16 split-K (kt_len = 3072 3-term / 2048 2-term).
// BM=128, BN=128, BK=32. 8 warps (2m x 4n), warp tile 64x32.
// cp.async 3-stage pipeline; smem stride 80B/row (conflict-free ldmatrix).
#define BM 128
#define BN 128
#define BK 32
#define SSTR 80
#define STG  (128*SSTR)        /* 10240 B per operand per stage */
#define STAGES 3
#define SMEM_DYN (STAGES*2*STG) /* 61440 B */

// tasks: 0=sim  1=X(z@Wq + agg@Wv)  2=inp(Xln@Wout, split-out)  3=gi(+b1)
//        4=gh(mem_t@Whh + b1)  5=out(memAt@Wmf + z + b1, batched over t)
__global__ __launch_bounds__(256,2) void gemm_mma(
    int task, int kt_len, int t, const float* __restrict__ b1,
    const float* __restrict__ zin, float* __restrict__ outp)
{
    extern __shared__ __align__(16) char smem[];
    const int tid  = threadIdx.x;
    const int wid  = tid >> 5, lane = tid & 31;
    const int brow = blockIdx.y * BM;
    const int bcol = blockIdx.x * BN;
    const int warp_m = (wid & 1) * 64;
    const int warp_n = (wid >> 1) * 32;

    const __nv_bfloat16 *A0=0, *A1=0, *W0=0, *W1=0;
    int nseg = 1, b = 0, w = 0, tt = 0;
    if (task == 0) {
        int bz = blockIdx.z; b = bz/21; int p = bz%21; tt = c_pt[p]; w = c_pw[p];
        A0 = g_znA + (size_t)((b*Tt+tt)*Mm + brow)*KT;
        W0 = g_znB + (size_t)((b*Tt+(tt-w))*Mm + bcol)*KT;
    } else if (task == 1) {
        A0 = g_zA   + (size_t)brow*KT; W0 = g_WqB + (size_t)bcol*KT;
        A1 = g_aggA + (size_t)brow*KT; W1 = g_WvB + (size_t)bcol*KT; nseg = 2;
    } else if (task == 2) {
        A0 = g_XlnA + (size_t)brow*KT; W0 = g_WoutB + (size_t)bcol*KT;
    } else if (task == 3) {
        A0 = g_inpA + (size_t)brow*KT; W0 = g_WihB + (size_t)bcol*KT;
    } else if (task == 4) {
        A0 = g_memAt + ((size_t)t*Bb*Mm + brow)*KT;
        W0 = g_WhhB + (size_t)bcol*KT;
    } else {
        A0 = g_memAt + (size_t)brow*KT;      // rows span all t (t-major)
        W0 = g_WmfB + (size_t)bcol*KT;
    }

    const uint32_t sbase = smem_u32(smem);

    const int lr  = tid >> 2;            // 0..63
    const int lc  = (tid & 3) * 8;       // element col within BK
    const uint32_t sts_off = (uint32_t)lr*SSTR + (uint32_t)(tid & 3)*16;

    const uint32_t aRow  = (uint32_t)(warp_m + (lane & 15));
    const uint32_t bRow  = (uint32_t)(warp_n + (lane & 15));
    const uint32_t chnk  = (uint32_t)((lane >> 4) * 16);

    float acc[4][4][4];
    #pragma unroll
    for (int i=0;i<4;i++)
      #pragma unroll
      for (int j=0;j<4;j++)
        #pragma unroll
        for (int k=0;k<4;k++) acc[i][j][k] = 0.f;

    const int SPS = kt_len / BK;         // stages per segment
    const int S = nseg * SPS;

    // issue cp.async for global stage sn into buffer sn%STAGES
    auto issue = [&](int sn){
        const int st  = sn % STAGES;
        const int seg = sn / SPS;
        const int k0  = (sn - seg*SPS) * BK;
        const __nv_bfloat16* Ab = (seg ? A1 : A0);
        const __nv_bfloat16* Wb = (seg ? W1 : W0);
        const uint32_t sa = sbase + (uint32_t)st*(2*STG) + sts_off;
        const uint32_t sb = sa + STG;
        cp16(sa,           Ab + (size_t)lr*KT      + k0 + lc);
        cp16(sa + 64*SSTR, Ab + (size_t)(lr+64)*KT + k0 + lc);
        cp16(sb,           Wb + (size_t)lr*KT      + k0 + lc);
        cp16(sb + 64*SSTR, Wb + (size_t)(lr+64)*KT + k0 + lc);
    };

    // prologue: stages 0..STAGES-2
    #pragma unroll
    for (int p = 0; p < STAGES-1; p++) { issue(p); CP_COMMIT(); }

    int buf = 0;
    for (int s = 0; s < S; s++) {
        CP_WAIT(STAGES-2);               // stage s resident (own copies)
        __syncthreads();                 // publish all threads' copies
        if (s + STAGES-1 < S) issue(s + STAGES-1);   // refill buffer just freed
        CP_COMMIT();
        const uint32_t sAb = sbase + (uint32_t)buf*(2*STG);
        const uint32_t sBb = sAb + STG;
        #pragma unroll
        for (int kk = 0; kk < 2; kk++) {
            uint32_t afr[4][4], bfr[2][4];
            #pragma unroll
            for (int mt = 0; mt < 4; mt++)
                LDSM4(afr[mt], sAb + (aRow + mt*16)*SSTR + kk*32 + chnk);
            #pragma unroll
            for (int nt = 0; nt < 2; nt++)
                LDSM4(bfr[nt], sBb + (bRow + nt*16)*SSTR + kk*32 + chnk);
            #pragma unroll
            for (int mt = 0; mt < 4; mt++)
                #pragma unroll
                for (int n8 = 0; n8 < 4; n8++)
                    MMA16816(acc[mt][n8], afr[mt],
                             bfr[n8>>1][n8&1], bfr[n8>>1][2+(n8&1)]);
        }
        buf = (buf == STAGES-1) ? 0 : buf + 1;
    }

    // ------------------------------ epilogue ----------------------------------
    const int l4 = lane >> 2;
    const int l2 = (lane & 3) * 2;
    #pragma unroll
    for (int mt = 0; mt < 4; mt++) {
        #pragma unroll
        for (int half = 0; half < 2; half++) {
            const int row = brow + warp_m + mt*16 + l4 + half*8;
            #pragma unroll
            for (int n8 = 0; n8 < 4; n8++) {
                const int col = bcol + warp_n + n8*8 + l2;
                float c0 = acc[mt][n8][half*2 + 0];
                float c1 = acc[mt][n8][half*2 + 1];
                if (task == 0) {
                    float* C = g_sim + (size_t)((b*Tt+tt)*Mm + row)*WM + w*Mm + col;
                    *(float2*)C = make_float2(c0, c1);
                } else if (task == 1) {
                    float* C = g_X + (size_t)row*Dd + col;
                    *(float2*)C = make_float2(c0, c1);
                } else if (task == 2) {
                    // consumer (task 3) is 3-term: write [hi|lo|hi]
                    __nv_bfloat16* dst = g_inpA + (size_t)row*KT + col;
                    __nv_bfloat16 h0,l0,h1,l1;
                    split2(c0, h0, l0); split2(c1, h1, l1);
                    __nv_bfloat162 hh; hh.x = h0; hh.y = h1;
                    __nv_bfloat162 ll; ll.x = l0; ll.y = l1;
                    *(__nv_bfloat162*)(dst)        = hh;
                    *(__nv_bfloat162*)(dst + 1024) = ll;
                    *(__nv_bfloat162*)(dst + 2048) = hh;
                } else if (task == 3) {
                    float2 bb = *(const float2*)(b1 + col);
                    float* C = g_gi + (size_t)row*(3*Hh) + col;
                    *(float2*)C = make_float2(c0 + bb.x, c1 + bb.y);
                } else if (task == 4) {
                    float2 bb = *(const float2*)(b1 + col);
                    float* C = g_gh + (size_t)row*(3*Hh) + col;
                    *(float2*)C = make_float2(c0 + bb.x, c1 + bb.y);
                } else {
                    const int tg = row >> 10;          // row = t*1024 + i
                    const int i  = row & 1023;
                    const int bi = i >> 9, m = i & 511;
                    const size_t zr = (size_t)((bi*Tt + tg)*Mm + m)*Dd + col;
                    float2 zz = *(const float2*)(zin + zr);
                    float2 bb = *(const float2*)(b1 + col);
                    *(float2*)(outp + zr) = make_float2(c0 + zz.x + bb.x,
                                                        c1 + zz.y + bb.y);
                }
            }
        }
    }
}

// ============================ conversion kernels ==============================
__global__ void k_convB(const float* __restrict__ src, __nv_bfloat16* __restrict__ dst)
{
    int e = blockIdx.x*256 + threadIdx.x;
    int r = e >> 10, c = e & 1023;
    __nv_bfloat16 h, l; split2(src[e], h, l);
    size_t base = (size_t)r*KT;
    dst[base + c] = h; dst[base + 1024 + c] = h; dst[base + 2048 + c] = l;
}

// ============================ elementwise kernels =============================
// normalize -> znA/znB splits; also write raw-z A-split
__global__ void k_normalize(const float* __restrict__ z)
{
    const int row = blockIdx.x, tid = threadIdx.x;
    __shared__ float red[256];
    const float* src = z + (size_t)row*Dd;
    float s = 0.f;
    for (int d = tid; d < Dd; d += 256) { float v = src[d]; s += v*v; }
    red[tid] = s; __syncthreads();
    for (int st = 128; st > 0; st >>= 1) { if (tid < st) red[tid] += red[tid+st]; __syncthreads(); }
    const float inv = 1.0f / fmaxf(sqrtf(red[0]), 1e-12f);
    const size_t base = (size_t)row*KT;
    for (int d = tid; d < Dd; d += 256) {
        float zr = src[d];
        float v = zr*inv;
        __nv_bfloat16 h, l; split2(v, h, l);
        g_znA[base + d] = h; g_znA[base + 1024 + d] = l; g_znA[base + 2048 + d] = h;
        g_znB[base + d] = h; g_znB[base + 1024 + d] = h; g_znB[base + 2048 + d] = l;
        __nv_bfloat16 zh, zl; split2(zr, zh, zl);
        g_zA[base + d] = zh; g_zA[base + 1024 + d] = zl; g_zA[base + 2048 + d] = zh;
    }
}

__global__ void k_wksum(const float* __restrict__ Wk)
{
    int d = blockIdx.x*blockDim.x + threadIdx.x;
    if (d < Dd) {
        float s = 0.f;
        for (int r = 0; r < Dd; r++) s += Wk[(size_t)r*Dd + d];
        g_wksum[d] = s;
    }
}

__global__ void k_s0(const float* __restrict__ z, const float* __restrict__ Watt_q)
{
    const int bt = blockIdx.x, tid = threadIdx.x;
    __shared__ float red[256];
    const float* src = z + (size_t)(bt*Mm)*Dd;
    float s = 0.f;
    for (int d = tid; d < Dd; d += 256) s += src[d]*Watt_q[d];
    red[tid] = s; __syncthreads();
    for (int st = 128; st > 0; st >>= 1) { if (tid < st) red[tid] += red[tid+st]; __syncthreads(); }
    if (tid == 0) g_s0[bt] = red[0];
}

// warp-shuffle argmax top-k (preserves smallest-index tie-break)
__global__ void k_topk(void)
{
    const int row = blockIdx.x, tid = threadIdx.x;
    const int t = (row / Mm) % Tt;
    const int limit = (t >= 2 ? 3 : t + 1) * Mm;
    const int lane = tid & 31, wid = tid >> 5;
    __shared__ float sv[WM];
    __shared__ float wv[8];
    __shared__ int   wx[8];
    for (int i = tid; i < limit; i += 256) sv[i] = g_sim[(size_t)row*WM + i];
    __syncthreads();
    for (int k = 0; k < KNN; k++) {
        float bv = -INFINITY; int bi = 0x7FFFFFFF;
        for (int i = tid; i < limit; i += 256) {
            float v = sv[i];
            if (v > bv) { bv = v; bi = i; }
        }
        #pragma unroll
        for (int o = 16; o > 0; o >>= 1) {
            float v2 = __shfl_down_sync(0xffffffff, bv, o);
            int   i2 = __shfl_down_sync(0xffffffff, bi, o);
            if (v2 > bv || (v2 == bv && i2 < bi)) { bv = v2; bi = i2; }
        }
        if (lane == 0) { wv[wid] = bv; wx[wid] = bi; }
        __syncthreads();
        if (tid == 0) {
            float fv = wv[0]; int fi = wx[0];
            #pragma unroll
            for (int j = 1; j < 8; j++)
                if (wv[j] > fv || (wv[j] == fv && wx[j] < fi)) { fv = wv[j]; fi = wx[j]; }
            g_vals[row*KNN+k] = fv;
            g_idx [row*KNN+k] = fi;
            sv[fi] = -INFINITY;
        }
        __syncthreads();
    }
}

__global__ void k_attn_agg(const float* __restrict__ z)
{
    const int row = blockIdx.x, tid = threadIdx.x;   // 128 threads
    const int bt = row / Mm;
    const int t = bt % Tt, b = bt / Tt;
    __shared__ float kf[KNN][Dd];
    __shared__ float red[128];
    __shared__ float kh[KNN], alpha[KNN];
    for (int k = 0; k < KNN; k++) {
        int id = g_idx[row*KNN+k];
        int w = id / Mm, j = id - w*Mm;
        int tt = t - w; if (tt < 0) tt = 0;
        const float* src = z + (size_t)((b*Tt+tt)*Mm + j)*Dd;
        float part = 0.f;
        for (int d = tid; d < Dd; d += 128) { float v = src[d]; kf[k][d] = v; part += v*g_wksum[d]; }
        red[tid] = part; __syncthreads();
        for (int s = 64; s > 0; s >>= 1) { if (tid < s) red[tid] += red[tid+s]; __syncthreads(); }
        if (tid == 0) kh[k] = red[0];
        __syncthreads();
    }
    if (tid == 0) {
        float s = g_s0[bt];
        float l[KNN], mx = -INFINITY;
        for (int k = 0; k < KNN; k++) { l[k] = s*kh[k]; mx = fmaxf(mx, l[k]); }
        float sum = 0.f;
        for (int k = 0; k < KNN; k++) { l[k] = expf(l[k]-mx); sum += l[k]; }
        for (int k = 0; k < KNN; k++)
            alpha[k] = 0.5f*g_vals[row*KNN+k] + 0.5f*(l[k]/sum);
    }
    __syncthreads();
    const size_t base = (size_t)row*KT;
    for (int d = tid; d < Dd; d += 128) {
        float a = 0.f;
        #pragma unroll
        for (int k = 0; k < KNN; k++) a += alpha[k]*kf[k][d];
        __nv_bfloat16 h, l; split2(a, h, l);
        g_aggA[base + d] = h; g_aggA[base + 1024 + d] = l; g_aggA[base + 2048 + d] = h;
    }
}

__global__ void k_layernorm(const float* __restrict__ lnw, const float* __restrict__ lnb)
{
    const int row = blockIdx.x, tid = threadIdx.x;
    __shared__ float xr[Dd];
    __shared__ float red[256];
    const float* p = g_X + (size_t)row*Dd;
    float s = 0.f;
    for (int d = tid; d < Dd; d += 256) { float v = p[d]; xr[d] = v; s += v; }
    red[tid] = s; __syncthreads();
    for (int st = 128; st > 0; st >>= 1) { if (tid < st) red[tid] += red[tid+st]; __syncthreads(); }
    const float mu = red[0] * (1.0f/Dd);
    __syncthreads();
    float v2 = 0.f;
    for (int d = tid; d < Dd; d += 256) { float dv = xr[d]-mu; v2 += dv*dv; }
    red[tid] = v2; __syncthreads();
    for (int st = 128; st > 0; st >>= 1) { if (tid < st) red[tid] += red[tid+st]; __syncthreads(); }
    const float inv = 1.0f / sqrtf(red[0]*(1.0f/Dd) + LN_EPS);
    const size_t base = (size_t)row*KT;
    for (int d = tid; d < Dd; d += 256) {
        float v = (xr[d]-mu)*inv*lnw[d] + lnb[d];
        __nv_bfloat16 h, l; split2(v, h, l);
        // consumer (task 2) is 3-term: write [hi|lo|hi]
        g_XlnA[base + d] = h; g_XlnA[base + 1024 + d] = l; g_XlnA[base + 2048 + d] = h;
    }
}

__global__ void k_zero_mem(void)
{
    int e = blockIdx.x*256 + threadIdx.x;
    if (e < Bb*Mm*Hh) g_mem[e] = 0.f;
}

__global__ void k_init_gh(const float* __restrict__ bhh)
{
    int e = blockIdx.x*256 + threadIdx.x;
    g_gh[e] = bhh[e % (3*Hh)];
}

__global__ void k_gru(int t, float* __restrict__ out_mem)
{
    const int e = blockIdx.x*256 + threadIdx.x;       // 0 .. B*M*H-1
    const int i = e >> 10;
    const int hc = e & (Hh-1);
    const int b = i >> 9;
    const size_t gir = (size_t)(i + b*(Tt-1)*Mm + t*Mm);
    const float* gi = g_gi + gir*(3*Hh);
    const float* gh = g_gh + (size_t)i*(3*Hh);
    float r  = 1.f/(1.f + expf(-(gi[hc]        + gh[hc])));
    float zg = 1.f/(1.f + expf(-(gi[Hh+hc]     + gh[Hh+hc])));
    float n  = tanhf(gi[2*Hh+hc] + r*gh[2*Hh+hc]);
    size_t mo = (size_t)i*Hh + hc;
    float old = g_mem[mo];
    float nm = (1.f - zg)*n + zg*old;
    g_mem[mo] = nm;
    __nv_bfloat16 h, l; split2(nm, h, l);
    // task 4 consumer is 3-term: write [hi|lo|hi] (task 5 reads 2-term prefix)
    const size_t base = ((size_t)t*Bb*Mm + i)*KT;
    g_memAt[base + hc] = h; g_memAt[base + 1024 + hc] = l; g_memAt[base + 2048 + hc] = h;
    if (t == Tt-1) out_mem[mo] = nm;     // fused final-mem output copy
}

// ================================ launch ======================================
extern "C" void kernel_launch(void* const* d_in, const int* in_sizes, int n_in,
                              void* d_out, int out_size)
{
    const float* z      = (const float*)d_in[0];
    const float* Wq     = (const float*)d_in[1];
    const float* Wv     = (const float*)d_in[2];
    const float* Wout   = (const float*)d_in[3];
    const float* ln_w   = (const float*)d_in[4];
    const float* ln_b   = (const float*)d_in[5];
    const float* Watt_q = (const float*)d_in[6];
    const float* Watt_k = (const float*)d_in[7];
    const float* W_ih   = (const float*)d_in[8];
    const float* W_hh   = (const float*)d_in[9];
    const float* b_ih   = (const float*)d_in[10];
    const float* b_hh   = (const float*)d_in[11];
    const float* W_mf   = (const float*)d_in[12];
    const float* b_mf   = (const float*)d_in[13];
    float* out     = (float*)d_out;
    float* out_h   = out;                            // (B,T,M,D)
    float* out_mem = out + (size_t)NROWS*Dd;         // (B,M,H)

    cudaFuncSetAttribute(gemm_mma, cudaFuncAttributeMaxDynamicSharedMemorySize, SMEM_DYN);

    __nv_bfloat16 *pWqB, *pWvB, *pWoutB, *pWihB, *pWhhB, *pWmfB;
    cudaGetSymbolAddress((void**)&pWqB,   g_WqB);
    cudaGetSymbolAddress((void**)&pWvB,   g_WvB);
    cudaGetSymbolAddress((void**)&pWoutB, g_WoutB);
    cudaGetSymbolAddress((void**)&pWihB,  g_WihB);
    cudaGetSymbolAddress((void**)&pWhhB,  g_WhhB);
    cudaGetSymbolAddress((void**)&pWmfB,  g_WmfB);

    // ---- conversions + parallel precompute ----
    k_normalize<<<NROWS, 256>>>(z);                  // also writes g_zA split
    k_convB<<<Dd*Dd/256, 256>>>(Wq,   pWqB);
    k_convB<<<Dd*Dd/256, 256>>>(Wv,   pWvB);
    k_convB<<<Dd*Dd/256, 256>>>(Wout, pWoutB);
    k_convB<<<3*Hh*Dd/256, 256>>>(W_ih, pWihB);
    k_convB<<<3*Hh*Dd/256, 256>>>(W_hh, pWhhB);
    k_convB<<<Dd*Dd/256, 256>>>(W_mf, pWmfB);
    k_wksum<<<Dd/256, 256>>>(Watt_k);
    k_s0<<<Bb*Tt, 256>>>(z, Watt_q);

    // sims (42 Gram blocks) — 3-term (top-k ordering needs precision)
    gemm_mma<<<dim3(Mm/BN, Mm/BM, Bb*21), 256, SMEM_DYN>>>(0, KT, 0, nullptr, nullptr, nullptr);
    k_topk<<<NROWS, 256>>>();
    k_attn_agg<<<NROWS, 128>>>(z);

    // X = z@Wq^T + agg@Wv^T  -> g_X  — 3-term
    gemm_mma<<<dim3(Dd/BN, NROWS/BM), 256, SMEM_DYN>>>(1, KT, 0, nullptr, nullptr, nullptr);
    k_layernorm<<<NROWS, 256>>>(ln_w, ln_b);
    // inp = Xln@Wout^T (split out) ; gi = inp@W_ih^T + b_ih — 3-term
    gemm_mma<<<dim3(Dd/BN, NROWS/BM), 256, SMEM_DYN>>>(2, KT, 0, nullptr, nullptr, nullptr);
    gemm_mma<<<dim3(3*Hh/BN, NROWS/BM), 256, SMEM_DYN>>>(3, KT, 0, b_ih, nullptr, nullptr);

    // ---- sequential GRU (gh-only GEMM, 3-term) ----
    k_zero_mem<<<(Bb*Mm*Hh)/256, 256>>>();
    k_init_gh<<<(Bb*Mm*3*Hh)/256, 256>>>(b_hh);
    for (int t = 0; t < Tt; t++) {
        k_gru<<<(Bb*Mm*Hh)/256, 256>>>(t, out_mem);  // mem <- mem_{t+1}, store memAt[t]
        if (t < Tt-1)                                 // gh for next step only
            gemm_mma<<<dim3(3*Hh/BN, (Bb*Mm)/BM), 256, SMEM_DYN>>>(4, KT, t, b_hh, nullptr, nullptr);
    }
    // out_h = z + mem_t@Wmf^T + b_mf  (batched over t) — 2-term (additive, ~3e-4)
    gemm_mma<<<dim3(Dd/BN, (Tt*Bb*Mm)/BM), 256, SMEM_DYN>>>(5, KT2, 0, b_mf, z, out_h);
}

// round 15
// speedup vs baseline: 1.2621x; 1.2269x over previous
#include <cuda_runtime.h>
#include <cuda_fp16.h>
#include <math.h>
#include <stdint.h>

// Problem constants
#define Bb 2
#define Tt 8
#define Mm 512
#define Dd 1024
#define Hh 1024
#define WIN 3
#define KNN 8
#define NROWS (Bb*Tt*Mm)      /* 8192 */
#define WM (WIN*Mm)           /* 1536 */
#define LN_EPS 1e-5f
#define KT 3072               /* 3-term: [hi|lo|hi] x [hi|hi|lo], err ~2^-22 (fp16) */
#define KT2 2048              /* 2-term prefix: [hi|lo] x [hi|hi], err ~2^-11 (fp16) */

// ---------------- scratch (device globals; no allocation allowed) -------------
__device__ float g_sim[(size_t)NROWS*WM];
__device__ float g_vals[NROWS*KNN];
__device__ int   g_idx[NROWS*KNN];
__device__ float g_X[NROWS*Dd];
__device__ float g_gi[(size_t)NROWS*3*Hh];
__device__ float g_gh[(size_t)Bb*Mm*3*Hh];
__device__ float g_mem[Bb*Mm*Hh];
__device__ float g_wksum[Dd];
__device__ float g_s0[Bb*Tt];

// fp16 split-K operand copies (16B aligned for cp.async 16B chunks)
__device__ __align__(16) __half g_znA[(size_t)NROWS*KT];
__device__ __align__(16) __half g_znB[(size_t)NROWS*KT];
__device__ __align__(16) __half g_zA [(size_t)NROWS*KT];
__device__ __align__(16) __half g_aggA[(size_t)NROWS*KT];
__device__ __align__(16) __half g_XlnA[(size_t)NROWS*KT];
__device__ __align__(16) __half g_inpA[(size_t)NROWS*KT];
__device__ __align__(16) __half g_memAt[(size_t)Tt*Bb*Mm*KT]; /* per-t mem */
__device__ __align__(16) __half g_WqB [(size_t)Dd*KT];
__device__ __align__(16) __half g_WvB [(size_t)Dd*KT];
__device__ __align__(16) __half g_WoutB[(size_t)Dd*KT];
__device__ __align__(16) __half g_WihB[(size_t)3*Hh*KT];
__device__ __align__(16) __half g_WhhB[(size_t)3*Hh*KT];
__device__ __align__(16) __half g_WmfB[(size_t)Dd*KT];

// valid (t, w) pairs
__constant__ int c_pt[21] = {0,1,1,2,2,2,3,3,3,4,4,4,5,5,5,6,6,6,7,7,7};
__constant__ int c_pw[21] = {0,0,1,0,1,2,0,1,2,0,1,2,0,1,2,0,1,2,0,1,2};

// ============================ helpers =========================================
__device__ __forceinline__ uint32_t smem_u32(const void* p){
    uint32_t a;
    asm("{ .reg .u64 t; cvta.to.shared.u64 t, %1; cvt.u32.u64 %0, t; }"
        : "=r"(a) : "l"(p));
    return a;
}
__device__ __forceinline__ void split2h(float x, __half& h, __half& l){
    h = __float2half_rn(x);
    l = __float2half_rn(x - __half2float(h));
}
__device__ __forceinline__ void cp16(uint32_t dst, const void* src){
    asm volatile("cp.async.cg.shared.global [%0], [%1], 16;"
                 :: "r"(dst), "l"(src));
}
#define CP_COMMIT() asm volatile("cp.async.commit_group;" ::: "memory")
#define CP_WAIT(n)  asm volatile("cp.async.wait_group %0;" :: "n"(n) : "memory")
#define LDSM4(r, a)                                                             \
    asm volatile("ldmatrix.sync.aligned.m8n8.x4.shared.b16 {%0,%1,%2,%3}, [%4];"\
        : "=r"((r)[0]), "=r"((r)[1]), "=r"((r)[2]), "=r"((r)[3]) : "r"(a))
#define MMA16816(c, a, b0v, b1v)                                                \
    asm volatile("mma.sync.aligned.m16n8k16.row.col.f32.f16.f16.f32 "           \
        "{%0,%1,%2,%3}, {%4,%5,%6,%7}, {%8,%9}, {%0,%1,%2,%3};"                 \
        : "+f"((c)[0]), "+f"((c)[1]), "+f"((c)[2]), "+f"((c)[3])                \
        : "r"((a)[0]), "r"((a)[1]), "r"((a)[2]), "r"((a)[3]),                   \
          "r"(b0v), "r"(b1v))

// ============================ mma.sync GEMM ===================================
// C[i,j] = sum A[i,:]*W[j,:], fp16 split-K (kt_len = 3072 3-term / 2048 2-term).
// BM=128, BN=128, BK=32. 8 warps (2m x 4n), warp tile 64x32.
// cp.async 3-stage pipeline; smem stride 80B/row (conflict-free ldmatrix).
#define BM 128
#define BN 128
#define BK 32
#define SSTR 80
#define STG  (128*SSTR)        /* 10240 B per operand per stage */
#define STAGES 3
#define SMEM_DYN (STAGES*2*STG) /* 61440 B */

// tasks: 0=sim  1=X(z@Wq + agg@Wv)  2=inp(Xln@Wout, split-out)  3=gi(+b1)
//        4=gh(mem_t@Whh + b1)  5=out(memAt@Wmf + z + b1, batched over t)
__global__ __launch_bounds__(256,2) void gemm_mma(
    int task, int kt_len, int t, const float* __restrict__ b1,
    const float* __restrict__ zin, float* __restrict__ outp)
{
    extern __shared__ __align__(16) char smem[];
    const int tid  = threadIdx.x;
    const int wid  = tid >> 5, lane = tid & 31;
    const int brow = blockIdx.y * BM;
    const int bcol = blockIdx.x * BN;
    const int warp_m = (wid & 1) * 64;
    const int warp_n = (wid >> 1) * 32;

    const __half *A0=0, *A1=0, *W0=0, *W1=0;
    int nseg = 1, b = 0, w = 0, tt = 0;
    if (task == 0) {
        int bz = blockIdx.z; b = bz/21; int p = bz%21; tt = c_pt[p]; w = c_pw[p];
        A0 = g_znA + (size_t)((b*Tt+tt)*Mm + brow)*KT;
        W0 = g_znB + (size_t)((b*Tt+(tt-w))*Mm + bcol)*KT;
    } else if (task == 1) {
        A0 = g_zA   + (size_t)brow*KT; W0 = g_WqB + (size_t)bcol*KT;
        A1 = g_aggA + (size_t)brow*KT; W1 = g_WvB + (size_t)bcol*KT; nseg = 2;
    } else if (task == 2) {
        A0 = g_XlnA + (size_t)brow*KT; W0 = g_WoutB + (size_t)bcol*KT;
    } else if (task == 3) {
        A0 = g_inpA + (size_t)brow*KT; W0 = g_WihB + (size_t)bcol*KT;
    } else if (task == 4) {
        A0 = g_memAt + ((size_t)t*Bb*Mm + brow)*KT;
        W0 = g_WhhB + (size_t)bcol*KT;
    } else {
        A0 = g_memAt + (size_t)brow*KT;      // rows span all t (t-major)
        W0 = g_WmfB + (size_t)bcol*KT;
    }

    const uint32_t sbase = smem_u32(smem);

    const int lr  = tid >> 2;            // 0..63
    const int lc  = (tid & 3) * 8;       // element col within BK
    const uint32_t sts_off = (uint32_t)lr*SSTR + (uint32_t)(tid & 3)*16;

    const uint32_t aRow  = (uint32_t)(warp_m + (lane & 15));
    const uint32_t bRow  = (uint32_t)(warp_n + (lane & 15));
    const uint32_t chnk  = (uint32_t)((lane >> 4) * 16);

    float acc[4][4][4];
    #pragma unroll
    for (int i=0;i<4;i++)
      #pragma unroll
      for (int j=0;j<4;j++)
        #pragma unroll
        for (int k=0;k<4;k++) acc[i][j][k] = 0.f;

    const int SPS = kt_len / BK;         // stages per segment
    const int S = nseg * SPS;

    // issue cp.async for global stage sn into buffer sn%STAGES
    auto issue = [&](int sn){
        const int st  = sn % STAGES;
        const int seg = sn / SPS;
        const int k0  = (sn - seg*SPS) * BK;
        const __half* Ab = (seg ? A1 : A0);
        const __half* Wb = (seg ? W1 : W0);
        const uint32_t sa = sbase + (uint32_t)st*(2*STG) + sts_off;
        const uint32_t sb = sa + STG;
        cp16(sa,           Ab + (size_t)lr*KT      + k0 + lc);
        cp16(sa + 64*SSTR, Ab + (size_t)(lr+64)*KT + k0 + lc);
        cp16(sb,           Wb + (size_t)lr*KT      + k0 + lc);
        cp16(sb + 64*SSTR, Wb + (size_t)(lr+64)*KT + k0 + lc);
    };

    // prologue: stages 0..STAGES-2
    #pragma unroll
    for (int p = 0; p < STAGES-1; p++) { issue(p); CP_COMMIT(); }

    int buf = 0;
    for (int s = 0; s < S; s++) {
        CP_WAIT(STAGES-2);               // stage s resident (own copies)
        __syncthreads();                 // publish all threads' copies
        if (s + STAGES-1 < S) issue(s + STAGES-1);   // refill buffer just freed
        CP_COMMIT();
        const uint32_t sAb = sbase + (uint32_t)buf*(2*STG);
        const uint32_t sBb = sAb + STG;
        #pragma unroll
        for (int kk = 0; kk < 2; kk++) {
            uint32_t afr[4][4], bfr[2][4];
            #pragma unroll
            for (int mt = 0; mt < 4; mt++)
                LDSM4(afr[mt], sAb + (aRow + mt*16)*SSTR + kk*32 + chnk);
            #pragma unroll
            for (int nt = 0; nt < 2; nt++)
                LDSM4(bfr[nt], sBb + (bRow + nt*16)*SSTR + kk*32 + chnk);
            #pragma unroll
            for (int mt = 0; mt < 4; mt++)
                #pragma unroll
                for (int n8 = 0; n8 < 4; n8++)
                    MMA16816(acc[mt][n8], afr[mt],
                             bfr[n8>>1][n8&1], bfr[n8>>1][2+(n8&1)]);
        }
        buf = (buf == STAGES-1) ? 0 : buf + 1;
    }

    // ------------------------------ epilogue ----------------------------------
    const int l4 = lane >> 2;
    const int l2 = (lane & 3) * 2;
    #pragma unroll
    for (int mt = 0; mt < 4; mt++) {
        #pragma unroll
        for (int half = 0; half < 2; half++) {
            const int row = brow + warp_m + mt*16 + l4 + half*8;
            #pragma unroll
            for (int n8 = 0; n8 < 4; n8++) {
                const int col = bcol + warp_n + n8*8 + l2;
                float c0 = acc[mt][n8][half*2 + 0];
                float c1 = acc[mt][n8][half*2 + 1];
                if (task == 0) {
                    float* C = g_sim + (size_t)((b*Tt+tt)*Mm + row)*WM + w*Mm + col;
                    *(float2*)C = make_float2(c0, c1);
                } else if (task == 1) {
                    float* C = g_X + (size_t)row*Dd + col;
                    *(float2*)C = make_float2(c0, c1);
                } else if (task == 2) {
                    // consumer (task 3) is 2-term: write [hi|lo]
                    __half* dst = g_inpA + (size_t)row*KT + col;
                    __half h0,l0,h1,l1;
                    split2h(c0, h0, l0); split2h(c1, h1, l1);
                    __half2 hh; hh.x = h0; hh.y = h1;
                    __half2 ll; ll.x = l0; ll.y = l1;
                    *(__half2*)(dst)        = hh;
                    *(__half2*)(dst + 1024) = ll;
                } else if (task == 3) {
                    float2 bb = *(const float2*)(b1 + col);
                    float* C = g_gi + (size_t)row*(3*Hh) + col;
                    *(float2*)C = make_float2(c0 + bb.x, c1 + bb.y);
                } else if (task == 4) {
                    float2 bb = *(const float2*)(b1 + col);
                    float* C = g_gh + (size_t)row*(3*Hh) + col;
                    *(float2*)C = make_float2(c0 + bb.x, c1 + bb.y);
                } else {
                    const int tg = row >> 10;          // row = t*1024 + i
                    const int i  = row & 1023;
                    const int bi = i >> 9, m = i & 511;
                    const size_t zr = (size_t)((bi*Tt + tg)*Mm + m)*Dd + col;
                    float2 zz = *(const float2*)(zin + zr);
                    float2 bb = *(const float2*)(b1 + col);
                    *(float2*)(outp + zr) = make_float2(c0 + zz.x + bb.x,
                                                        c1 + zz.y + bb.y);
                }
            }
        }
    }
}

// ============================ conversion kernels ==============================
__global__ void k_convB(const float* __restrict__ src, __half* __restrict__ dst)
{
    int e = blockIdx.x*256 + threadIdx.x;
    int r = e >> 10, c = e & 1023;
    __half h, l; split2h(src[e], h, l);
    size_t base = (size_t)r*KT;
    dst[base + c] = h; dst[base + 1024 + c] = h; dst[base + 2048 + c] = l;
}

// ============================ elementwise kernels =============================
// normalize -> znA/znB splits (3-term); also raw-z A-split (3-term, task 1)
__global__ void k_normalize(const float* __restrict__ z)
{
    const int row = blockIdx.x, tid = threadIdx.x;
    __shared__ float red[256];
    const float* src = z + (size_t)row*Dd;
    float s = 0.f;
    for (int d = tid; d < Dd; d += 256) { float v = src[d]; s += v*v; }
    red[tid] = s; __syncthreads();
    for (int st = 128; st > 0; st >>= 1) { if (tid < st) red[tid] += red[tid+st]; __syncthreads(); }
    const float inv = 1.0f / fmaxf(sqrtf(red[0]), 1e-12f);
    const size_t base = (size_t)row*KT;
    for (int d = tid; d < Dd; d += 256) {
        float zr = src[d];
        float v = zr*inv;
        __half h, l; split2h(v, h, l);
        g_znA[base + d] = h; g_znA[base + 1024 + d] = l; g_znA[base + 2048 + d] = h;
        g_znB[base + d] = h; g_znB[base + 1024 + d] = h; g_znB[base + 2048 + d] = l;
        __half zh, zl; split2h(zr, zh, zl);
        g_zA[base + d] = zh; g_zA[base + 1024 + d] = zl; g_zA[base + 2048 + d] = zh;
    }
}

__global__ void k_wksum(const float* __restrict__ Wk)
{
    int d = blockIdx.x*blockDim.x + threadIdx.x;
    if (d < Dd) {
        float s = 0.f;
        for (int r = 0; r < Dd; r++) s += Wk[(size_t)r*Dd + d];
        g_wksum[d] = s;
    }
}

__global__ void k_s0(const float* __restrict__ z, const float* __restrict__ Watt_q)
{
    const int bt = blockIdx.x, tid = threadIdx.x;
    __shared__ float red[256];
    const float* src = z + (size_t)(bt*Mm)*Dd;
    float s = 0.f;
    for (int d = tid; d < Dd; d += 256) s += src[d]*Watt_q[d];
    red[tid] = s; __syncthreads();
    for (int st = 128; st > 0; st >>= 1) { if (tid < st) red[tid] += red[tid+st]; __syncthreads(); }
    if (tid == 0) g_s0[bt] = red[0];
}

// warp-shuffle argmax top-k (preserves smallest-index tie-break)
__global__ void k_topk(void)
{
    const int row = blockIdx.x, tid = threadIdx.x;
    const int t = (row / Mm) % Tt;
    const int limit = (t >= 2 ? 3 : t + 1) * Mm;
    const int lane = tid & 31, wid = tid >> 5;
    __shared__ float sv[WM];
    __shared__ float wv[8];
    __shared__ int   wx[8];
    for (int i = tid; i < limit; i += 256) sv[i] = g_sim[(size_t)row*WM + i];
    __syncthreads();
    for (int k = 0; k < KNN; k++) {
        float bv = -INFINITY; int bi = 0x7FFFFFFF;
        for (int i = tid; i < limit; i += 256) {
            float v = sv[i];
            if (v > bv) { bv = v; bi = i; }
        }
        #pragma unroll
        for (int o = 16; o > 0; o >>= 1) {
            float v2 = __shfl_down_sync(0xffffffff, bv, o);
            int   i2 = __shfl_down_sync(0xffffffff, bi, o);
            if (v2 > bv || (v2 == bv && i2 < bi)) { bv = v2; bi = i2; }
        }
        if (lane == 0) { wv[wid] = bv; wx[wid] = bi; }
        __syncthreads();
        if (tid == 0) {
            float fv = wv[0]; int fi = wx[0];
            #pragma unroll
            for (int j = 1; j < 8; j++)
                if (wv[j] > fv || (wv[j] == fv && wx[j] < fi)) { fv = wv[j]; fi = wx[j]; }
            g_vals[row*KNN+k] = fv;
            g_idx [row*KNN+k] = fi;
            sv[fi] = -INFINITY;
        }
        __syncthreads();
    }
}

__global__ void k_attn_agg(const float* __restrict__ z)
{
    const int row = blockIdx.x, tid = threadIdx.x;   // 128 threads
    const int bt = row / Mm;
    const int t = bt % Tt, b = bt / Tt;
    __shared__ float kf[KNN][Dd];
    __shared__ float red[128];
    __shared__ float kh[KNN], alpha[KNN];
    for (int k = 0; k < KNN; k++) {
        int id = g_idx[row*KNN+k];
        int w = id / Mm, j = id - w*Mm;
        int tt = t - w; if (tt < 0) tt = 0;
        const float* src = z + (size_t)((b*Tt+tt)*Mm + j)*Dd;
        float part = 0.f;
        for (int d = tid; d < Dd; d += 128) { float v = src[d]; kf[k][d] = v; part += v*g_wksum[d]; }
        red[tid] = part; __syncthreads();
        for (int s = 64; s > 0; s >>= 1) { if (tid < s) red[tid] += red[tid+s]; __syncthreads(); }
        if (tid == 0) kh[k] = red[0];
        __syncthreads();
    }
    if (tid == 0) {
        float s = g_s0[bt];
        float l[KNN], mx = -INFINITY;
        for (int k = 0; k < KNN; k++) { l[k] = s*kh[k]; mx = fmaxf(mx, l[k]); }
        float sum = 0.f;
        for (int k = 0; k < KNN; k++) { l[k] = expf(l[k]-mx); sum += l[k]; }
        for (int k = 0; k < KNN; k++)
            alpha[k] = 0.5f*g_vals[row*KNN+k] + 0.5f*(l[k]/sum);
    }
    __syncthreads();
    const size_t base = (size_t)row*KT;
    for (int d = tid; d < Dd; d += 128) {
        float a = 0.f;
        #pragma unroll
        for (int k = 0; k < KNN; k++) a += alpha[k]*kf[k][d];
        __half h, l; split2h(a, h, l);
        g_aggA[base + d] = h; g_aggA[base + 1024 + d] = l; g_aggA[base + 2048 + d] = h;
    }
}

__global__ void k_layernorm(const float* __restrict__ lnw, const float* __restrict__ lnb)
{
    const int row = blockIdx.x, tid = threadIdx.x;
    __shared__ float xr[Dd];
    __shared__ float red[256];
    const float* p = g_X + (size_t)row*Dd;
    float s = 0.f;
    for (int d = tid; d < Dd; d += 256) { float v = p[d]; xr[d] = v; s += v; }
    red[tid] = s; __syncthreads();
    for (int st = 128; st > 0; st >>= 1) { if (tid < st) red[tid] += red[tid+st]; __syncthreads(); }
    const float mu = red[0] * (1.0f/Dd);
    __syncthreads();
    float v2 = 0.f;
    for (int d = tid; d < Dd; d += 256) { float dv = xr[d]-mu; v2 += dv*dv; }
    red[tid] = v2; __syncthreads();
    for (int st = 128; st > 0; st >>= 1) { if (tid < st) red[tid] += red[tid+st]; __syncthreads(); }
    const float inv = 1.0f / sqrtf(red[0]*(1.0f/Dd) + LN_EPS);
    const size_t base = (size_t)row*KT;
    for (int d = tid; d < Dd; d += 256) {
        float v = (xr[d]-mu)*inv*lnw[d] + lnb[d];
        __half h, l; split2h(v, h, l);
        // consumer (task 2) is 2-term: write [hi|lo]
        g_XlnA[base + d] = h; g_XlnA[base + 1024 + d] = l;
    }
}

__global__ void k_zero_mem(void)
{
    int e = blockIdx.x*256 + threadIdx.x;
    if (e < Bb*Mm*Hh) g_mem[e] = 0.f;
}

__global__ void k_init_gh(const float* __restrict__ bhh)
{
    int e = blockIdx.x*256 + threadIdx.x;
    g_gh[e] = bhh[e % (3*Hh)];
}

__global__ void k_gru(int t, float* __restrict__ out_mem)
{
    const int e = blockIdx.x*256 + threadIdx.x;       // 0 .. B*M*H-1
    const int i = e >> 10;
    const int hc = e & (Hh-1);
    const int b = i >> 9;
    const size_t gir = (size_t)(i + b*(Tt-1)*Mm + t*Mm);
    const float* gi = g_gi + gir*(3*Hh);
    const float* gh = g_gh + (size_t)i*(3*Hh);
    float r  = 1.f/(1.f + expf(-(gi[hc]        + gh[hc])));
    float zg = 1.f/(1.f + expf(-(gi[Hh+hc]     + gh[Hh+hc])));
    float n  = tanhf(gi[2*Hh+hc] + r*gh[2*Hh+hc]);
    size_t mo = (size_t)i*Hh + hc;
    float old = g_mem[mo];
    float nm = (1.f - zg)*n + zg*old;
    g_mem[mo] = nm;
    __half h, l; split2h(nm, h, l);
    // consumers (tasks 4,5) are 2-term: write [hi|lo]
    const size_t base = ((size_t)t*Bb*Mm + i)*KT;
    g_memAt[base + hc] = h; g_memAt[base + 1024 + hc] = l;
    if (t == Tt-1) out_mem[mo] = nm;     // fused final-mem output copy
}

// ================================ launch ======================================
extern "C" void kernel_launch(void* const* d_in, const int* in_sizes, int n_in,
                              void* d_out, int out_size)
{
    const float* z      = (const float*)d_in[0];
    const float* Wq     = (const float*)d_in[1];
    const float* Wv     = (const float*)d_in[2];
    const float* Wout   = (const float*)d_in[3];
    const float* ln_w   = (const float*)d_in[4];
    const float* ln_b   = (const float*)d_in[5];
    const float* Watt_q = (const float*)d_in[6];
    const float* Watt_k = (const float*)d_in[7];
    const float* W_ih   = (const float*)d_in[8];
    const float* W_hh   = (const float*)d_in[9];
    const float* b_ih   = (const float*)d_in[10];
    const float* b_hh   = (const float*)d_in[11];
    const float* W_mf   = (const float*)d_in[12];
    const float* b_mf   = (const float*)d_in[13];
    float* out     = (float*)d_out;
    float* out_h   = out;                            // (B,T,M,D)
    float* out_mem = out + (size_t)NROWS*Dd;         // (B,M,H)

    cudaFuncSetAttribute(gemm_mma, cudaFuncAttributeMaxDynamicSharedMemorySize, SMEM_DYN);

    __half *pWqB, *pWvB, *pWoutB, *pWihB, *pWhhB, *pWmfB;
    cudaGetSymbolAddress((void**)&pWqB,   g_WqB);
    cudaGetSymbolAddress((void**)&pWvB,   g_WvB);
    cudaGetSymbolAddress((void**)&pWoutB, g_WoutB);
    cudaGetSymbolAddress((void**)&pWihB,  g_WihB);
    cudaGetSymbolAddress((void**)&pWhhB,  g_WhhB);
    cudaGetSymbolAddress((void**)&pWmfB,  g_WmfB);

    // ---- conversions + parallel precompute ----
    k_normalize<<<NROWS, 256>>>(z);                  // also writes g_zA split
    k_convB<<<Dd*Dd/256, 256>>>(Wq,   pWqB);
    k_convB<<<Dd*Dd/256, 256>>>(Wv,   pWvB);
    k_convB<<<Dd*Dd/256, 256>>>(Wout, pWoutB);
    k_convB<<<3*Hh*Dd/256, 256>>>(W_ih, pWihB);
    k_convB<<<3*Hh*Dd/256, 256>>>(W_hh, pWhhB);
    k_convB<<<Dd*Dd/256, 256>>>(W_mf, pWmfB);
    k_wksum<<<Dd/256, 256>>>(Watt_k);
    k_s0<<<Bb*Tt, 256>>>(z, Watt_q);

    // sims (42 Gram blocks) — fp16 3-term (top-k ordering; err ~2^-22)
    gemm_mma<<<dim3(Mm/BN, Mm/BM, Bb*21), 256, SMEM_DYN>>>(0, KT, 0, nullptr, nullptr, nullptr);
    k_topk<<<NROWS, 256>>>();
    k_attn_agg<<<NROWS, 128>>>(z);

    // X = z@Wq^T + agg@Wv^T  -> g_X  — fp16 3-term (feeds LayerNorm)
    gemm_mma<<<dim3(Dd/BN, NROWS/BM), 256, SMEM_DYN>>>(1, KT, 0, nullptr, nullptr, nullptr);
    k_layernorm<<<NROWS, 256>>>(ln_w, ln_b);
    // inp = Xln@Wout^T (split out) ; gi = inp@W_ih^T + b_ih — fp16 2-term (~4.9e-4/GEMM)
    gemm_mma<<<dim3(Dd/BN, NROWS/BM), 256, SMEM_DYN>>>(2, KT2, 0, nullptr, nullptr, nullptr);
    gemm_mma<<<dim3(3*Hh/BN, NROWS/BM), 256, SMEM_DYN>>>(3, KT2, 0, b_ih, nullptr, nullptr);

    // ---- sequential GRU (gh-only GEMM, fp16 2-term) ----
    k_zero_mem<<<(Bb*Mm*Hh)/256, 256>>>();
    k_init_gh<<<(Bb*Mm*3*Hh)/256, 256>>>(b_hh);
    for (int t = 0; t < Tt; t++) {
        k_gru<<<(Bb*Mm*Hh)/256, 256>>>(t, out_mem);  // mem <- mem_{t+1}, store memAt[t]
        if (t < Tt-1)                                 // gh for next step only
            gemm_mma<<<dim3(3*Hh/BN, (Bb*Mm)/BM), 256, SMEM_DYN>>>(4, KT2, t, b_hh, nullptr, nullptr);
    }
    // out_h = z + mem_t@Wmf^T + b_mf  (batched over t) — fp16 2-term
    gemm_mma<<<dim3(Dd/BN, (Tt*Bb*Mm)/BM), 256, SMEM_DYN>>>(5, KT2, 0, b_mf, z, out_h);
}

// round 16
// speedup vs baseline: 1.3773x; 1.0913x over previous
#include <cuda_runtime.h>
#include <cuda_fp16.h>
#include <math.h>
#include <stdint.h>

// Problem constants
#define Bb 2
#define Tt 8
#define Mm 512
#define Dd 1024
#define Hh 1024
#define WIN 3
#define KNN 8
#define NROWS (Bb*Tt*Mm)      /* 8192 */
#define WM (WIN*Mm)           /* 1536 */
#define LN_EPS 1e-5f
#define KT 3072               /* 3-term: [hi|lo|hi] x [hi|hi|lo], err ~2^-22 (fp16) */
#define KT2 2048              /* 2-term prefix: [hi|lo] x [hi|hi], err ~2^-11 (fp16) */

// ---------------- scratch (device globals; no allocation allowed) -------------
__device__ float g_sim[(size_t)NROWS*WM];
__device__ float g_vals[NROWS*KNN];
__device__ int   g_idx[NROWS*KNN];
__device__ float g_X[NROWS*Dd];
__device__ float g_gi[(size_t)NROWS*3*Hh];
__device__ float g_gh[(size_t)Bb*Mm*3*Hh];
__device__ float g_mem[Bb*Mm*Hh];
__device__ float g_wksum[Dd];
__device__ float g_wkpart[8*Dd];
__device__ float g_s0[Bb*Tt];

// fp16 split-K operand copies (16B aligned for cp.async 16B chunks)
__device__ __align__(16) __half g_znA[(size_t)NROWS*KT];
__device__ __align__(16) __half g_znB[(size_t)NROWS*KT];
__device__ __align__(16) __half g_zA [(size_t)NROWS*KT];
__device__ __align__(16) __half g_aggA[(size_t)NROWS*KT];
__device__ __align__(16) __half g_XlnA[(size_t)NROWS*KT];
__device__ __align__(16) __half g_WfB [(size_t)NROWS*KT];   /* Wfused B-layout (3072 rows used) */
__device__ __align__(16) __half g_memAt[(size_t)Tt*Bb*Mm*KT]; /* per-t mem */
__device__ __align__(16) __half g_WqB [(size_t)Dd*KT];
__device__ __align__(16) __half g_WvB [(size_t)Dd*KT];
__device__ __align__(16) __half g_WoutB[(size_t)Dd*KT];     /* Wout^T B-layout */
__device__ __align__(16) __half g_WihA[(size_t)3*Hh*KT];    /* W_ih A-layout */
__device__ __align__(16) __half g_WhhB[(size_t)3*Hh*KT];
__device__ __align__(16) __half g_WmfB[(size_t)Dd*KT];

// valid (t, w) pairs
__constant__ int c_pt[21] = {0,1,1,2,2,2,3,3,3,4,4,4,5,5,5,6,6,6,7,7,7};
__constant__ int c_pw[21] = {0,0,1,0,1,2,0,1,2,0,1,2,0,1,2,0,1,2,0,1,2};

// ============================ helpers =========================================
__device__ __forceinline__ uint32_t smem_u32(const void* p){
    uint32_t a;
    asm("{ .reg .u64 t; cvta.to.shared.u64 t, %1; cvt.u32.u64 %0, t; }"
        : "=r"(a) : "l"(p));
    return a;
}
__device__ __forceinline__ void split2h(float x, __half& h, __half& l){
    h = __float2half_rn(x);
    l = __float2half_rn(x - __half2float(h));
}
__device__ __forceinline__ void cp16(uint32_t dst, const void* src){
    asm volatile("cp.async.cg.shared.global [%0], [%1], 16;"
                 :: "r"(dst), "l"(src));
}
#define CP_COMMIT() asm volatile("cp.async.commit_group;" ::: "memory")
#define CP_WAIT(n)  asm volatile("cp.async.wait_group %0;" :: "n"(n) : "memory")
#define LDSM4(r, a)                                                             \
    asm volatile("ldmatrix.sync.aligned.m8n8.x4.shared.b16 {%0,%1,%2,%3}, [%4];"\
        : "=r"((r)[0]), "=r"((r)[1]), "=r"((r)[2]), "=r"((r)[3]) : "r"(a))
#define MMA16816(c, a, b0v, b1v)                                                \
    asm volatile("mma.sync.aligned.m16n8k16.row.col.f32.f16.f16.f32 "           \
        "{%0,%1,%2,%3}, {%4,%5,%6,%7}, {%8,%9}, {%0,%1,%2,%3};"                 \
        : "+f"((c)[0]), "+f"((c)[1]), "+f"((c)[2]), "+f"((c)[3])                \
        : "r"((a)[0]), "r"((a)[1]), "r"((a)[2]), "r"((a)[3]),                   \
          "r"(b0v), "r"(b1v))

// ============================ mma.sync GEMM ===================================
// C[i,j] = sum A[i,:]*W[j,:], fp16 split-K (kt_len = 3072 3-term / 2048 2-term).
// BM=128, BN=128, BK=32. 8 warps (2m x 4n), warp tile 64x32.
// cp.async 3-stage pipeline; smem stride 80B/row (conflict-free ldmatrix).
#define BM 128
#define BN 128
#define BK 32
#define SSTR 80
#define STG  (128*SSTR)        /* 10240 B per operand per stage */
#define STAGES 3
#define SMEM_DYN (STAGES*2*STG) /* 61440 B */

// tasks: 0=sim  1=X(z@Wq + agg@Wv)  2=Wfused(W_ih@WoutT, split-out)
//        3=gi(Xln@Wfused + b1)  4=gh(mem_t@Whh + b1)  5=out(memAt@Wmf + z + b1)
__global__ __launch_bounds__(256,2) void gemm_mma(
    int task, int kt_len, int t, const float* __restrict__ b1,
    const float* __restrict__ zin, float* __restrict__ outp)
{
    extern __shared__ __align__(16) char smem[];
    const int tid  = threadIdx.x;
    const int wid  = tid >> 5, lane = tid & 31;
    const int brow = blockIdx.y * BM;
    const int bcol = blockIdx.x * BN;
    const int warp_m = (wid & 1) * 64;
    const int warp_n = (wid >> 1) * 32;

    const __half *A0=0, *A1=0, *W0=0, *W1=0;
    int nseg = 1, b = 0, w = 0, tt = 0;
    if (task == 0) {
        int bz = blockIdx.z; b = bz/21; int p = bz%21; tt = c_pt[p]; w = c_pw[p];
        A0 = g_znA + (size_t)((b*Tt+tt)*Mm + brow)*KT;
        W0 = g_znB + (size_t)((b*Tt+(tt-w))*Mm + bcol)*KT;
    } else if (task == 1) {
        A0 = g_zA   + (size_t)brow*KT; W0 = g_WqB + (size_t)bcol*KT;
        A1 = g_aggA + (size_t)brow*KT; W1 = g_WvB + (size_t)bcol*KT; nseg = 2;
    } else if (task == 2) {
        A0 = g_WihA + (size_t)brow*KT; W0 = g_WoutB + (size_t)bcol*KT;
    } else if (task == 3) {
        A0 = g_XlnA + (size_t)brow*KT; W0 = g_WfB + (size_t)bcol*KT;
    } else if (task == 4) {
        A0 = g_memAt + ((size_t)t*Bb*Mm + brow)*KT;
        W0 = g_WhhB + (size_t)bcol*KT;
    } else {
        A0 = g_memAt + (size_t)brow*KT;      // rows span all t (t-major)
        W0 = g_WmfB + (size_t)bcol*KT;
    }

    const uint32_t sbase = smem_u32(smem);

    const int lr  = tid >> 2;            // 0..63
    const int lc  = (tid & 3) * 8;       // element col within BK
    const uint32_t sts_off = (uint32_t)lr*SSTR + (uint32_t)(tid & 3)*16;

    const uint32_t aRow  = (uint32_t)(warp_m + (lane & 15));
    const uint32_t bRow  = (uint32_t)(warp_n + (lane & 15));
    const uint32_t chnk  = (uint32_t)((lane >> 4) * 16);

    float acc[4][4][4];
    #pragma unroll
    for (int i=0;i<4;i++)
      #pragma unroll
      for (int j=0;j<4;j++)
        #pragma unroll
        for (int k=0;k<4;k++) acc[i][j][k] = 0.f;

    const int SPS = kt_len / BK;         // stages per segment
    const int S = nseg * SPS;

    // issue cp.async for global stage sn into buffer sn%STAGES
    auto issue = [&](int sn){
        const int st  = sn % STAGES;
        const int seg = sn / SPS;
        const int k0  = (sn - seg*SPS) * BK;
        const __half* Ab = (seg ? A1 : A0);
        const __half* Wb = (seg ? W1 : W0);
        const uint32_t sa = sbase + (uint32_t)st*(2*STG) + sts_off;
        const uint32_t sb = sa + STG;
        cp16(sa,           Ab + (size_t)lr*KT      + k0 + lc);
        cp16(sa + 64*SSTR, Ab + (size_t)(lr+64)*KT + k0 + lc);
        cp16(sb,           Wb + (size_t)lr*KT      + k0 + lc);
        cp16(sb + 64*SSTR, Wb + (size_t)(lr+64)*KT + k0 + lc);
    };

    // prologue: stages 0..STAGES-2
    #pragma unroll
    for (int p = 0; p < STAGES-1; p++) { issue(p); CP_COMMIT(); }

    int buf = 0;
    for (int s = 0; s < S; s++) {
        CP_WAIT(STAGES-2);               // stage s resident (own copies)
        __syncthreads();                 // publish all threads' copies
        if (s + STAGES-1 < S) issue(s + STAGES-1);   // refill buffer just freed
        CP_COMMIT();
        const uint32_t sAb = sbase + (uint32_t)buf*(2*STG);
        const uint32_t sBb = sAb + STG;
        #pragma unroll
        for (int kk = 0; kk < 2; kk++) {
            uint32_t afr[4][4], bfr[2][4];
            #pragma unroll
            for (int mt = 0; mt < 4; mt++)
                LDSM4(afr[mt], sAb + (aRow + mt*16)*SSTR + kk*32 + chnk);
            #pragma unroll
            for (int nt = 0; nt < 2; nt++)
                LDSM4(bfr[nt], sBb + (bRow + nt*16)*SSTR + kk*32 + chnk);
            #pragma unroll
            for (int mt = 0; mt < 4; mt++)
                #pragma unroll
                for (int n8 = 0; n8 < 4; n8++)
                    MMA16816(acc[mt][n8], afr[mt],
                             bfr[n8>>1][n8&1], bfr[n8>>1][2+(n8&1)]);
        }
        buf = (buf == STAGES-1) ? 0 : buf + 1;
    }

    // ------------------------------ epilogue ----------------------------------
    const int l4 = lane >> 2;
    const int l2 = (lane & 3) * 2;
    #pragma unroll
    for (int mt = 0; mt < 4; mt++) {
        #pragma unroll
        for (int half = 0; half < 2; half++) {
            const int row = brow + warp_m + mt*16 + l4 + half*8;
            #pragma unroll
            for (int n8 = 0; n8 < 4; n8++) {
                const int col = bcol + warp_n + n8*8 + l2;
                float c0 = acc[mt][n8][half*2 + 0];
                float c1 = acc[mt][n8][half*2 + 1];
                if (task == 0) {
                    float* C = g_sim + (size_t)((b*Tt+tt)*Mm + row)*WM + w*Mm + col;
                    *(float2*)C = make_float2(c0, c1);
                } else if (task == 1) {
                    float* C = g_X + (size_t)row*Dd + col;
                    *(float2*)C = make_float2(c0, c1);
                } else if (task == 2) {
                    // Wfused row 'row' (3H), col 'col' (D); consumer is 2-term: [hi|hi]
                    __half* dst = g_WfB + (size_t)row*KT + col;
                    __half h0,l0,h1,l1;
                    split2h(c0, h0, l0); split2h(c1, h1, l1);
                    __half2 hh; hh.x = h0; hh.y = h1;
                    *(__half2*)(dst)        = hh;
                    *(__half2*)(dst + 1024) = hh;
                } else if (task == 3) {
                    float2 bb = *(const float2*)(b1 + col);
                    float* C = g_gi + (size_t)row*(3*Hh) + col;
                    *(float2*)C = make_float2(c0 + bb.x, c1 + bb.y);
                } else if (task == 4) {
                    float2 bb = *(const float2*)(b1 + col);
                    float* C = g_gh + (size_t)row*(3*Hh) + col;
                    *(float2*)C = make_float2(c0 + bb.x, c1 + bb.y);
                } else {
                    const int tg = row >> 10;          // row = t*1024 + i
                    const int i  = row & 1023;
                    const int bi = i >> 9, m = i & 511;
                    const size_t zr = (size_t)((bi*Tt + tg)*Mm + m)*Dd + col;
                    float2 zz = *(const float2*)(zin + zr);
                    float2 bb = *(const float2*)(b1 + col);
                    *(float2*)(outp + zr) = make_float2(c0 + zz.x + bb.x,
                                                        c1 + zz.y + bb.y);
                }
            }
        }
    }
}

// ============================ conversion kernels ==============================
// B-layout [hi|hi|lo]
__global__ void k_convB(const float* __restrict__ src, __half* __restrict__ dst)
{
    int e = blockIdx.x*256 + threadIdx.x;
    int r = e >> 10, c = e & 1023;
    __half h, l; split2h(src[e], h, l);
    size_t base = (size_t)r*KT;
    dst[base + c] = h; dst[base + 1024 + c] = h; dst[base + 2048 + c] = l;
}
// A-layout [hi|lo|hi]
__global__ void k_convA(const float* __restrict__ src, __half* __restrict__ dst)
{
    int e = blockIdx.x*256 + threadIdx.x;
    int r = e >> 10, c = e & 1023;
    __half h, l; split2h(src[e], h, l);
    size_t base = (size_t)r*KT;
    dst[base + c] = h; dst[base + 1024 + c] = l; dst[base + 2048 + c] = h;
}
// transposed B-layout: dst row j holds src[:,j] split [hi|hi|lo] (tiled transpose)
__global__ void k_convBT(const float* __restrict__ src, __half* __restrict__ dst)
{
    __shared__ float tbuf[32][33];
    const int tx = threadIdx.x & 31, ty = threadIdx.x >> 5;   // 32 x 8
    const int bj = blockIdx.x*32, bk = blockIdx.y*32;
    #pragma unroll
    for (int i = 0; i < 32; i += 8)
        tbuf[ty+i][tx] = src[(size_t)(bk+ty+i)*Dd + bj+tx];   // [k-local][j-local]
    __syncthreads();
    #pragma unroll
    for (int i = 0; i < 32; i += 8) {
        int j = bj + ty + i, k = bk + tx;
        float v = tbuf[tx][ty+i];
        __half h, l; split2h(v, h, l);
        size_t base = (size_t)j*KT;
        dst[base + k] = h; dst[base + 1024 + k] = h; dst[base + 2048 + k] = l;
    }
}

// ============================ elementwise kernels =============================
// normalize -> znA/znB (3-term, sim); raw-z A-split (2-term prefix used by task 1)
__global__ void k_normalize(const float* __restrict__ z)
{
    const int row = blockIdx.x, tid = threadIdx.x;
    __shared__ float red[256];
    const float* src = z + (size_t)row*Dd;
    float s = 0.f;
    for (int d = tid; d < Dd; d += 256) { float v = src[d]; s += v*v; }
    red[tid] = s; __syncthreads();
    for (int st = 128; st > 0; st >>= 1) { if (tid < st) red[tid] += red[tid+st]; __syncthreads(); }
    const float inv = 1.0f / fmaxf(sqrtf(red[0]), 1e-12f);
    const size_t base = (size_t)row*KT;
    for (int d = tid; d < Dd; d += 256) {
        float zr = src[d];
        float v = zr*inv;
        __half h, l; split2h(v, h, l);
        g_znA[base + d] = h; g_znA[base + 1024 + d] = l; g_znA[base + 2048 + d] = h;
        g_znB[base + d] = h; g_znB[base + 1024 + d] = h; g_znB[base + 2048 + d] = l;
        __half zh, zl; split2h(zr, zh, zl);
        g_zA[base + d] = zh; g_zA[base + 1024 + d] = zl;
    }
}

// column sums of Watt_k, deterministic two-phase
__global__ void k_wksum1(const float* __restrict__ Wk)
{
    int d = blockIdx.x*256 + threadIdx.x;
    int part = blockIdx.y;
    float s = 0.f;
    for (int r = part*128; r < part*128 + 128; r++) s += Wk[(size_t)r*Dd + d];
    g_wkpart[part*Dd + d] = s;
}
__global__ void k_wksum2(void)
{
    int d = blockIdx.x*256 + threadIdx.x;
    float s = 0.f;
    #pragma unroll
    for (int p = 0; p < 8; p++) s += g_wkpart[p*Dd + d];
    g_wksum[d] = s;
}

__global__ void k_s0(const float* __restrict__ z, const float* __restrict__ Watt_q)
{
    const int bt = blockIdx.x, tid = threadIdx.x;
    __shared__ float red[256];
    const float* src = z + (size_t)(bt*Mm)*Dd;
    float s = 0.f;
    for (int d = tid; d < Dd; d += 256) s += src[d]*Watt_q[d];
    red[tid] = s; __syncthreads();
    for (int st = 128; st > 0; st >>= 1) { if (tid < st) red[tid] += red[tid+st]; __syncthreads(); }
    if (tid == 0) g_s0[bt] = red[0];
}

// warp-shuffle argmax top-k (preserves smallest-index tie-break)
__global__ void k_topk(void)
{
    const int row = blockIdx.x, tid = threadIdx.x;
    const int t = (row / Mm) % Tt;
    const int limit = (t >= 2 ? 3 : t + 1) * Mm;
    const int lane = tid & 31, wid = tid >> 5;
    __shared__ float sv[WM];
    __shared__ float wv[8];
    __shared__ int   wx[8];
    for (int i = tid; i < limit; i += 256) sv[i] = g_sim[(size_t)row*WM + i];
    __syncthreads();
    for (int k = 0; k < KNN; k++) {
        float bv = -INFINITY; int bi = 0x7FFFFFFF;
        for (int i = tid; i < limit; i += 256) {
            float v = sv[i];
            if (v > bv) { bv = v; bi = i; }
        }
        #pragma unroll
        for (int o = 16; o > 0; o >>= 1) {
            float v2 = __shfl_down_sync(0xffffffff, bv, o);
            int   i2 = __shfl_down_sync(0xffffffff, bi, o);
            if (v2 > bv || (v2 == bv && i2 < bi)) { bv = v2; bi = i2; }
        }
        if (lane == 0) { wv[wid] = bv; wx[wid] = bi; }
        __syncthreads();
        if (tid == 0) {
            float fv = wv[0]; int fi = wx[0];
            #pragma unroll
            for (int j = 1; j < 8; j++)
                if (wv[j] > fv || (wv[j] == fv && wx[j] < fi)) { fv = wv[j]; fi = wx[j]; }
            g_vals[row*KNN+k] = fv;
            g_idx [row*KNN+k] = fi;
            sv[fi] = -INFINITY;
        }
        __syncthreads();
    }
}

__global__ void k_attn_agg(const float* __restrict__ z)
{
    const int row = blockIdx.x, tid = threadIdx.x;   // 128 threads
    const int bt = row / Mm;
    const int t = bt % Tt, b = bt / Tt;
    __shared__ float kf[KNN][Dd];
    __shared__ float red[128];
    __shared__ float kh[KNN], alpha[KNN];
    for (int k = 0; k < KNN; k++) {
        int id = g_idx[row*KNN+k];
        int w = id / Mm, j = id - w*Mm;
        int tt = t - w; if (tt < 0) tt = 0;
        const float* src = z + (size_t)((b*Tt+tt)*Mm + j)*Dd;
        float part = 0.f;
        for (int d = tid; d < Dd; d += 128) { float v = src[d]; kf[k][d] = v; part += v*g_wksum[d]; }
        red[tid] = part; __syncthreads();
        for (int s = 64; s > 0; s >>= 1) { if (tid < s) red[tid] += red[tid+s]; __syncthreads(); }
        if (tid == 0) kh[k] = red[0];
        __syncthreads();
    }
    if (tid == 0) {
        float s = g_s0[bt];
        float l[KNN], mx = -INFINITY;
        for (int k = 0; k < KNN; k++) { l[k] = s*kh[k]; mx = fmaxf(mx, l[k]); }
        float sum = 0.f;
        for (int k = 0; k < KNN; k++) { l[k] = expf(l[k]-mx); sum += l[k]; }
        for (int k = 0; k < KNN; k++)
            alpha[k] = 0.5f*g_vals[row*KNN+k] + 0.5f*(l[k]/sum);
    }
    __syncthreads();
    const size_t base = (size_t)row*KT;
    for (int d = tid; d < Dd; d += 128) {
        float a = 0.f;
        #pragma unroll
        for (int k = 0; k < KNN; k++) a += alpha[k]*kf[k][d];
        __half h, l; split2h(a, h, l);
        // task 1 is 2-term: [hi|lo] only
        g_aggA[base + d] = h; g_aggA[base + 1024 + d] = l;
    }
}

__global__ void k_layernorm(const float* __restrict__ lnw, const float* __restrict__ lnb)
{
    const int row = blockIdx.x, tid = threadIdx.x;
    __shared__ float xr[Dd];
    __shared__ float red[256];
    const float* p = g_X + (size_t)row*Dd;
    float s = 0.f;
    for (int d = tid; d < Dd; d += 256) { float v = p[d]; xr[d] = v; s += v; }
    red[tid] = s; __syncthreads();
    for (int st = 128; st > 0; st >>= 1) { if (tid < st) red[tid] += red[tid+st]; __syncthreads(); }
    const float mu = red[0] * (1.0f/Dd);
    __syncthreads();
    float v2 = 0.f;
    for (int d = tid; d < Dd; d += 256) { float dv = xr[d]-mu; v2 += dv*dv; }
    red[tid] = v2; __syncthreads();
    for (int st = 128; st > 0; st >>= 1) { if (tid < st) red[tid] += red[tid+st]; __syncthreads(); }
    const float inv = 1.0f / sqrtf(red[0]*(1.0f/Dd) + LN_EPS);
    const size_t base = (size_t)row*KT;
    for (int d = tid; d < Dd; d += 256) {
        float v = (xr[d]-mu)*inv*lnw[d] + lnb[d];
        __half h, l; split2h(v, h, l);
        // consumer (task 3) is 2-term: write [hi|lo]
        g_XlnA[base + d] = h; g_XlnA[base + 1024 + d] = l;
    }
}

__global__ void k_zero_mem(void)
{
    int e = blockIdx.x*256 + threadIdx.x;
    if (e < Bb*Mm*Hh) g_mem[e] = 0.f;
}

__global__ void k_init_gh(const float* __restrict__ bhh)
{
    int e = blockIdx.x*256 + threadIdx.x;
    g_gh[e] = bhh[e % (3*Hh)];
}

__global__ void k_gru(int t, float* __restrict__ out_mem)
{
    const int e = blockIdx.x*256 + threadIdx.x;       // 0 .. B*M*H-1
    const int i = e >> 10;
    const int hc = e & (Hh-1);
    const int b = i >> 9;
    const size_t gir = (size_t)(i + b*(Tt-1)*Mm + t*Mm);
    const float* gi = g_gi + gir*(3*Hh);
    const float* gh = g_gh + (size_t)i*(3*Hh);
    float r  = 1.f/(1.f + expf(-(gi[hc]        + gh[hc])));
    float zg = 1.f/(1.f + expf(-(gi[Hh+hc]     + gh[Hh+hc])));
    float n  = tanhf(gi[2*Hh+hc] + r*gh[2*Hh+hc]);
    size_t mo = (size_t)i*Hh + hc;
    float old = g_mem[mo];
    float nm = (1.f - zg)*n + zg*old;
    g_mem[mo] = nm;
    __half h, l; split2h(nm, h, l);
    // consumers (tasks 4,5) are 2-term: write [hi|lo]
    const size_t base = ((size_t)t*Bb*Mm + i)*KT;
    g_memAt[base + hc] = h; g_memAt[base + 1024 + hc] = l;
    if (t == Tt-1) out_mem[mo] = nm;     // fused final-mem output copy
}

// ================================ launch ======================================
extern "C" void kernel_launch(void* const* d_in, const int* in_sizes, int n_in,
                              void* d_out, int out_size)
{
    const float* z      = (const float*)d_in[0];
    const float* Wq     = (const float*)d_in[1];
    const float* Wv     = (const float*)d_in[2];
    const float* Wout   = (const float*)d_in[3];
    const float* ln_w   = (const float*)d_in[4];
    const float* ln_b   = (const float*)d_in[5];
    const float* Watt_q = (const float*)d_in[6];
    const float* Watt_k = (const float*)d_in[7];
    const float* W_ih   = (const float*)d_in[8];
    const float* W_hh   = (const float*)d_in[9];
    const float* b_ih   = (const float*)d_in[10];
    const float* b_hh   = (const float*)d_in[11];
    const float* W_mf   = (const float*)d_in[12];
    const float* b_mf   = (const float*)d_in[13];
    float* out     = (float*)d_out;
    float* out_h   = out;                            // (B,T,M,D)
    float* out_mem = out + (size_t)NROWS*Dd;         // (B,M,H)

    cudaFuncSetAttribute(gemm_mma, cudaFuncAttributeMaxDynamicSharedMemorySize, SMEM_DYN);

    __half *pWqB, *pWvB, *pWoutB, *pWihA, *pWhhB, *pWmfB;
    cudaGetSymbolAddress((void**)&pWqB,   g_WqB);
    cudaGetSymbolAddress((void**)&pWvB,   g_WvB);
    cudaGetSymbolAddress((void**)&pWoutB, g_WoutB);
    cudaGetSymbolAddress((void**)&pWihA,  g_WihA);
    cudaGetSymbolAddress((void**)&pWhhB,  g_WhhB);
    cudaGetSymbolAddress((void**)&pWmfB,  g_WmfB);

    // ---- conversions + fused-weight precompute ----
    k_normalize<<<NROWS, 256>>>(z);                  // znA/znB + zA splits
    k_convA<<<3*Hh*Dd/256, 256>>>(W_ih, pWihA);      // W_ih A-layout
    k_convBT<<<dim3(Dd/32, Dd/32), 256>>>(Wout, pWoutB); // Wout^T B-layout
    // Wfused = W_ih @ Wout  (3-term, err ~2^-22) -> g_WfB [hi|hi]
    gemm_mma<<<dim3(Dd/BN, 3*Hh/BM), 256, SMEM_DYN>>>(2, KT, 0, nullptr, nullptr, nullptr);
    k_convB<<<Dd*Dd/256, 256>>>(Wq,   pWqB);
    k_convB<<<Dd*Dd/256, 256>>>(Wv,   pWvB);
    k_convB<<<3*Hh*Dd/256, 256>>>(W_hh, pWhhB);
    k_convB<<<Dd*Dd/256, 256>>>(W_mf, pWmfB);
    k_wksum1<<<dim3(Dd/256, 8), 256>>>(Watt_k);
    k_wksum2<<<Dd/256, 256>>>();
    k_s0<<<Bb*Tt, 256>>>(z, Watt_q);

    // sims (42 Gram blocks) — fp16 3-term (top-k ordering; err ~2^-22)
    gemm_mma<<<dim3(Mm/BN, Mm/BM, Bb*21), 256, SMEM_DYN>>>(0, KT, 0, nullptr, nullptr, nullptr);
    k_topk<<<NROWS, 256>>>();
    k_attn_agg<<<NROWS, 128>>>(z);

    // X = z@Wq^T + agg@Wv^T  -> g_X  — fp16 2-term
    gemm_mma<<<dim3(Dd/BN, NROWS/BM), 256, SMEM_DYN>>>(1, KT2, 0, nullptr, nullptr, nullptr);
    k_layernorm<<<NROWS, 256>>>(ln_w, ln_b);
    // gi = Xln@Wfused^T + b_ih — fused, fp16 2-term
    gemm_mma<<<dim3(3*Hh/BN, NROWS/BM), 256, SMEM_DYN>>>(3, KT2, 0, b_ih, nullptr, nullptr);

    // ---- sequential GRU (gh-only GEMM, fp16 2-term) ----
    k_zero_mem<<<(Bb*Mm*Hh)/256, 256>>>();
    k_init_gh<<<(Bb*Mm*3*Hh)/256, 256>>>(b_hh);
    for (int t = 0; t < Tt; t++) {
        k_gru<<<(Bb*Mm*Hh)/256, 256>>>(t, out_mem);  // mem <- mem_{t+1}, store memAt[t]
        if (t < Tt-1)                                 // gh for next step only
            gemm_mma<<<dim3(3*Hh/BN, (Bb*Mm)/BM), 256, SMEM_DYN>>>(4, KT2, t, b_hh, nullptr, nullptr);
    }
    // out_h = z + mem_t@Wmf^T + b_mf  (batched over t) — fp16 2-term
    gemm_mma<<<dim3(Dd/BN, (Tt*Bb*Mm)/BM), 256, SMEM_DYN>>>(5, KT2, 0, b_mf, z, out_h);
}